// round 1
// baseline (speedup 1.0000x reference)
#include <cuda_runtime.h>
#include <math.h>

// ---------------------------------------------------------------------------
// Problem constants
// ---------------------------------------------------------------------------
#define BB 2
#define SS 2048
#define DD 1024
#define HH 16
#define DKK 64
#define DFF 4096
#define WINDOW 128
#define NGLOBAL 16
#define MM (BB * SS)   // 4096 rows

// ---------------------------------------------------------------------------
// Scratch (device globals; no allocation allowed)
// ---------------------------------------------------------------------------
__device__ float g_xn [MM * DD];
__device__ float g_q  [MM * DD];
__device__ float g_k  [MM * DD];
__device__ float g_v  [MM * DD];
__device__ float g_att[MM * DD];
__device__ float g_x1 [MM * DD];
__device__ float g_xn2[MM * DD];
__device__ float g_h  [MM * DFF];

// ---------------------------------------------------------------------------
// LayerNorm: one block per row of 1024, 256 threads
// ---------------------------------------------------------------------------
__device__ __forceinline__ float block_reduce_sum(float v, float* sh) {
    int lane = threadIdx.x & 31;
    int wid  = threadIdx.x >> 5;
    #pragma unroll
    for (int o = 16; o > 0; o >>= 1) v += __shfl_down_sync(0xffffffffu, v, o);
    if (lane == 0) sh[wid] = v;
    __syncthreads();
    if (wid == 0) {
        float t = (lane < 8) ? sh[lane] : 0.0f;
        #pragma unroll
        for (int o = 4; o > 0; o >>= 1) t += __shfl_down_sync(0xffffffffu, t, o);
        if (lane == 0) sh[0] = t;
    }
    __syncthreads();
    float r = sh[0];
    __syncthreads();
    return r;
}

__global__ void __launch_bounds__(256) ln_kernel(const float* __restrict__ x,
                                                 const float* __restrict__ g,
                                                 const float* __restrict__ b,
                                                 float* __restrict__ y) {
    __shared__ float sh[32];
    const int row = blockIdx.x;
    const float* xr = x + (size_t)row * DD;
    float v[4];
    float s = 0.0f;
    #pragma unroll
    for (int i = 0; i < 4; i++) { v[i] = xr[threadIdx.x + 256 * i]; s += v[i]; }
    s = block_reduce_sum(s, sh);
    const float mean = s * (1.0f / DD);
    float sq = 0.0f;
    #pragma unroll
    for (int i = 0; i < 4; i++) { float d = v[i] - mean; sq += d * d; }
    sq = block_reduce_sum(sq, sh);
    const float rstd = rsqrtf(sq * (1.0f / DD) + 1e-5f);
    float* yr = y + (size_t)row * DD;
    #pragma unroll
    for (int i = 0; i < 4; i++) {
        int c = threadIdx.x + 256 * i;
        yr[c] = (v[i] - mean) * rstd * g[c] + b[c];
    }
}

// ---------------------------------------------------------------------------
// SGEMM: C[M,N] = A[M,K] @ B[K,N] + bias[N]  (+ epilogue)
// 128x128 block tile, BK=8, 256 threads, 8x8 per thread.
// EPI: 0 = none, 1 = exact GELU, 2 = residual add
// M,N,K must be multiples of 128/128/8 (all our shapes are).
// ---------------------------------------------------------------------------
template<int EPI>
__global__ void __launch_bounds__(256) sgemm_kernel(
        const float* __restrict__ A, const float* __restrict__ B,
        const float* __restrict__ bias, const float* __restrict__ resid,
        float* __restrict__ C, int M, int N, int K) {
    __shared__ float As[8][128];
    __shared__ float Bs[8][128];

    const int bm = blockIdx.y * 128;
    const int bn = blockIdx.x * 128;
    const int tid = threadIdx.x;

    const int arow = tid >> 1;          // 0..127
    const int acol = (tid & 1) * 4;     // 0 or 4
    const int brow = tid >> 5;          // 0..7
    const int bcol = (tid & 31) * 4;    // 0..124

    const int ty = tid >> 4;            // 0..15
    const int tx = tid & 15;            // 0..15

    const float* Aptr = A + (size_t)(bm + arow) * K + acol;
    const float* Bptr = B + (size_t)brow * N + bn + bcol;

    float acc[8][8];
    #pragma unroll
    for (int i = 0; i < 8; i++)
        #pragma unroll
        for (int j = 0; j < 8; j++) acc[i][j] = 0.0f;

    for (int k0 = 0; k0 < K; k0 += 8) {
        float4 av = *(const float4*)(Aptr + k0);
        float4 bv = *(const float4*)(Bptr + (size_t)k0 * N);
        As[acol + 0][arow] = av.x;
        As[acol + 1][arow] = av.y;
        As[acol + 2][arow] = av.z;
        As[acol + 3][arow] = av.w;
        *(float4*)&Bs[brow][bcol] = bv;
        __syncthreads();
        #pragma unroll
        for (int k = 0; k < 8; k++) {
            float a[8], bb[8];
            *(float4*)(a)     = *(const float4*)&As[k][ty * 8];
            *(float4*)(a + 4) = *(const float4*)&As[k][ty * 8 + 4];
            *(float4*)(bb)     = *(const float4*)&Bs[k][tx * 8];
            *(float4*)(bb + 4) = *(const float4*)&Bs[k][tx * 8 + 4];
            #pragma unroll
            for (int i = 0; i < 8; i++)
                #pragma unroll
                for (int j = 0; j < 8; j++)
                    acc[i][j] += a[i] * bb[j];
        }
        __syncthreads();
    }

    #pragma unroll
    for (int i = 0; i < 8; i++) {
        const int row = bm + ty * 8 + i;
        #pragma unroll
        for (int j4 = 0; j4 < 8; j4 += 4) {
            const int col = bn + tx * 8 + j4;
            float4 c;
            c.x = acc[i][j4 + 0] + bias[col + 0];
            c.y = acc[i][j4 + 1] + bias[col + 1];
            c.z = acc[i][j4 + 2] + bias[col + 2];
            c.w = acc[i][j4 + 3] + bias[col + 3];
            if (EPI == 1) {  // exact GELU
                c.x = 0.5f * c.x * (1.0f + erff(c.x * 0.70710678118654752f));
                c.y = 0.5f * c.y * (1.0f + erff(c.y * 0.70710678118654752f));
                c.z = 0.5f * c.z * (1.0f + erff(c.z * 0.70710678118654752f));
                c.w = 0.5f * c.w * (1.0f + erff(c.w * 0.70710678118654752f));
            }
            if (EPI == 2) {  // residual add
                float4 r = *(const float4*)(resid + (size_t)row * N + col);
                c.x += r.x; c.y += r.y; c.z += r.z; c.w += r.w;
            }
            *(float4*)(C + (size_t)row * N + col) = c;
        }
    }
}

// ---------------------------------------------------------------------------
// Masked attention (flash-style, fp32, online softmax)
// Grid: (S/16, H, B). Block: 256 threads.
// Each block: 16 queries for one (b,h); loops over 64-key chunks that
// intersect the local+global mask.
// q,k,v,o layouts are [B,S,D] with column = h*64 + d.
// ---------------------------------------------------------------------------
__global__ void __launch_bounds__(256) attn_kernel(
        const float* __restrict__ Q, const float* __restrict__ K,
        const float* __restrict__ V, float* __restrict__ O) {
    __shared__ float Qs[16][65];
    __shared__ float Ks[64][64];
    __shared__ float Vs[64][64];
    __shared__ float Ss[16][65];
    __shared__ float mS[16], lS[16], scS[16];

    const int qc = blockIdx.x;
    const int h  = blockIdx.y;
    const int b  = blockIdx.z;
    const int qbase = qc * 16;
    const int tid = threadIdx.x;

    // Load Q tile, pre-scaled by 1/sqrt(DK)
    for (int e = tid; e < 16 * 64; e += 256) {
        int qi = e >> 6, d = e & 63;
        Qs[qi][d] = Q[(size_t)(b * SS + qbase + qi) * DD + h * DKK + d] * 0.125f;
    }
    if (tid < 16) { mS[tid] = -INFINITY; lS[tid] = 0.0f; }

    const int oq = tid & 15;        // query handled in O-accumulate
    const int og = tid >> 4;        // dim group: og*4 .. og*4+3
    const int sq = tid & 15;        // query handled in score phase
    const int sg = tid >> 4;        // key group: sg*4 .. sg*4+3
    float acc[4] = {0.f, 0.f, 0.f, 0.f};

    __syncthreads();

    for (int c = 0; c < SS / 64; c++) {
        // does chunk c intersect this q-tile's allowed key set?
        bool use = (c == 0) || (qbase < NGLOBAL) ||
                   (64 * c + 63 >= qbase - WINDOW && 64 * c <= qbase + 15 + WINDOW);
        if (!use) continue;

        __syncthreads();  // previous iteration finished reading Ks/Vs/Ss
        for (int e = tid; e < 64 * 64; e += 256) {
            int r = e >> 6, d = e & 63;
            size_t gi = (size_t)(b * SS + 64 * c + r) * DD + h * DKK + d;
            Ks[r][d] = K[gi];
            Vs[r][d] = V[gi];
        }
        __syncthreads();

        // scores: thread (sq, sg) -> keys sg*4..sg*4+3 for query sq
        const int i = qbase + sq;
        #pragma unroll
        for (int kk = 0; kk < 4; kk++) {
            const int kr = sg * 4 + kk;
            const int j = 64 * c + kr;
            const bool ok = (abs(i - j) <= WINDOW) || (i < NGLOBAL) || (j < NGLOBAL);
            float s = -INFINITY;
            if (ok) {
                s = 0.0f;
                #pragma unroll
                for (int d = 0; d < 64; d++) s += Qs[sq][d] * Ks[kr][d];
            }
            Ss[sq][kr] = s;
        }
        __syncthreads();

        // per-query softmax bookkeeping (16 leader threads)
        if (tid < 16) {
            float mx = mS[tid];
            #pragma unroll 8
            for (int k2 = 0; k2 < 64; k2++) mx = fmaxf(mx, Ss[tid][k2]);
            const float sc = expf(mS[tid] - mx);   // 0 on first chunk (mS=-inf)
            float l = lS[tid] * sc;
            #pragma unroll 8
            for (int k2 = 0; k2 < 64; k2++) {
                float p = expf(Ss[tid][k2] - mx);  // masked: exp(-inf)=0
                Ss[tid][k2] = p;
                l += p;
            }
            mS[tid] = mx; lS[tid] = l; scS[tid] = sc;
        }
        __syncthreads();

        // rescale + accumulate P @ V
        const float sc = scS[oq];
        #pragma unroll
        for (int dd = 0; dd < 4; dd++) acc[dd] *= sc;
        #pragma unroll 8
        for (int k2 = 0; k2 < 64; k2++) {
            const float p = Ss[oq][k2];
            #pragma unroll
            for (int dd = 0; dd < 4; dd++)
                acc[dd] += p * Vs[k2][og * 4 + dd];
        }
    }

    const float inv = 1.0f / lS[oq];
    float* op = O + (size_t)(b * SS + qbase + oq) * DD + h * DKK + og * 4;
    #pragma unroll
    for (int dd = 0; dd < 4; dd++) op[dd] = acc[dd] * inv;
}

// ---------------------------------------------------------------------------
// Launch
// ---------------------------------------------------------------------------
extern "C" void kernel_launch(void* const* d_in, const int* in_sizes, int n_in,
                              void* d_out, int out_size) {
    const float* x     = (const float*)d_in[0];
    const float* Wq    = (const float*)d_in[1];
    const float* bq    = (const float*)d_in[2];
    const float* Wk    = (const float*)d_in[3];
    const float* bk    = (const float*)d_in[4];
    const float* Wv    = (const float*)d_in[5];
    const float* bv    = (const float*)d_in[6];
    const float* Wo    = (const float*)d_in[7];
    const float* bo    = (const float*)d_in[8];
    const float* ln1_g = (const float*)d_in[9];
    const float* ln1_b = (const float*)d_in[10];
    const float* W1    = (const float*)d_in[11];
    const float* b1    = (const float*)d_in[12];
    const float* W2    = (const float*)d_in[13];
    const float* b2    = (const float*)d_in[14];
    const float* ln2_g = (const float*)d_in[15];
    const float* ln2_b = (const float*)d_in[16];
    float* out = (float*)d_out;

    float *xn, *q, *k, *v, *att, *x1, *xn2, *hbuf;
    cudaGetSymbolAddress((void**)&xn,   g_xn);
    cudaGetSymbolAddress((void**)&q,    g_q);
    cudaGetSymbolAddress((void**)&k,    g_k);
    cudaGetSymbolAddress((void**)&v,    g_v);
    cudaGetSymbolAddress((void**)&att,  g_att);
    cudaGetSymbolAddress((void**)&x1,   g_x1);
    cudaGetSymbolAddress((void**)&xn2,  g_xn2);
    cudaGetSymbolAddress((void**)&hbuf, g_h);

    // 1) xn = LN(x)
    ln_kernel<<<MM, 256>>>(x, ln1_g, ln1_b, xn);

    // 2) q,k,v = xn @ W{q,k,v} + b
    dim3 g1(DD / 128, MM / 128);
    sgemm_kernel<0><<<g1, 256>>>(xn, Wq, bq, nullptr, q, MM, DD, DD);
    sgemm_kernel<0><<<g1, 256>>>(xn, Wk, bk, nullptr, k, MM, DD, DD);
    sgemm_kernel<0><<<g1, 256>>>(xn, Wv, bv, nullptr, v, MM, DD, DD);

    // 3) masked attention
    attn_kernel<<<dim3(SS / 16, HH, BB), 256>>>(q, k, v, att);

    // 4) x1 = x + att @ Wo + bo
    sgemm_kernel<2><<<g1, 256>>>(att, Wo, bo, x, x1, MM, DD, DD);

    // 5) xn2 = LN(x1)
    ln_kernel<<<MM, 256>>>(x1, ln2_g, ln2_b, xn2);

    // 6) h = gelu(xn2 @ W1 + b1)
    dim3 g2(DFF / 128, MM / 128);
    sgemm_kernel<1><<<g2, 256>>>(xn2, W1, b1, nullptr, hbuf, MM, DFF, DD);

    // 7) out = x1 + h @ W2 + b2
    sgemm_kernel<2><<<g1, 256>>>(hbuf, W2, b2, x1, out, MM, DD, DFF);
}

// round 2
// speedup vs baseline: 1.9180x; 1.9180x over previous
#include <cuda_runtime.h>
#include <math.h>
#include <stdint.h>

// ---------------------------------------------------------------------------
// Problem constants
// ---------------------------------------------------------------------------
#define BB 2
#define SS 2048
#define DD 1024
#define HH 16
#define DKK 64
#define DFF 4096
#define WINDOW 128
#define NGLOBAL 16
#define MM (BB * SS)   // 4096 rows

// ---------------------------------------------------------------------------
// Scratch (device globals; no allocation allowed)
// ---------------------------------------------------------------------------
__device__ float g_xn [MM * DD];
__device__ float g_q  [MM * DD];
__device__ float g_k  [MM * DD];
__device__ float g_v  [MM * DD];
__device__ float g_att[MM * DD];
__device__ float g_x1 [MM * DD];
__device__ float g_xn2[MM * DD];
__device__ float g_h  [MM * DFF];

// ---------------------------------------------------------------------------
// PTX helpers
// ---------------------------------------------------------------------------
__device__ __forceinline__ uint32_t f2tf32(float x) {
    uint32_t r;
    asm("cvt.rna.tf32.f32 %0, %1;" : "=r"(r) : "f"(x));
    return r;
}

__device__ __forceinline__ void mma_tf32(float c[4], const uint32_t a[4], const uint32_t b[2]) {
    asm volatile(
        "mma.sync.aligned.m16n8k8.row.col.f32.tf32.tf32.f32 "
        "{%0,%1,%2,%3}, {%4,%5,%6,%7}, {%8,%9}, {%0,%1,%2,%3};\n"
        : "+f"(c[0]), "+f"(c[1]), "+f"(c[2]), "+f"(c[3])
        : "r"(a[0]), "r"(a[1]), "r"(a[2]), "r"(a[3]), "r"(b[0]), "r"(b[1]));
}

__device__ __forceinline__ void cp_async16(float* smem_dst, const float* gmem_src) {
    uint32_t s = (uint32_t)__cvta_generic_to_shared(smem_dst);
    asm volatile("cp.async.cg.shared.global [%0], [%1], 16;\n" :: "r"(s), "l"(gmem_src));
}
__device__ __forceinline__ void cp_async_commit() {
    asm volatile("cp.async.commit_group;\n");
}
template<int N>
__device__ __forceinline__ void cp_async_wait() {
    asm volatile("cp.async.wait_group %0;\n" :: "n"(N));
}

__device__ __forceinline__ float gelu_exact(float x) {
    return 0.5f * x * (1.0f + erff(x * 0.70710678118654752f));
}

// ---------------------------------------------------------------------------
// LayerNorm: one block per row of 1024, 256 threads
// ---------------------------------------------------------------------------
__device__ __forceinline__ float block_reduce_sum(float v, float* sh) {
    int lane = threadIdx.x & 31;
    int wid  = threadIdx.x >> 5;
    #pragma unroll
    for (int o = 16; o > 0; o >>= 1) v += __shfl_down_sync(0xffffffffu, v, o);
    if (lane == 0) sh[wid] = v;
    __syncthreads();
    if (wid == 0) {
        float t = (lane < 8) ? sh[lane] : 0.0f;
        #pragma unroll
        for (int o = 4; o > 0; o >>= 1) t += __shfl_down_sync(0xffffffffu, t, o);
        if (lane == 0) sh[0] = t;
    }
    __syncthreads();
    float r = sh[0];
    __syncthreads();
    return r;
}

__global__ void __launch_bounds__(256) ln_kernel(const float* __restrict__ x,
                                                 const float* __restrict__ g,
                                                 const float* __restrict__ b,
                                                 float* __restrict__ y) {
    __shared__ float sh[32];
    const int row = blockIdx.x;
    const float* xr = x + (size_t)row * DD;
    float v[4];
    float s = 0.0f;
    #pragma unroll
    for (int i = 0; i < 4; i++) { v[i] = xr[threadIdx.x + 256 * i]; s += v[i]; }
    s = block_reduce_sum(s, sh);
    const float mean = s * (1.0f / DD);
    float sq = 0.0f;
    #pragma unroll
    for (int i = 0; i < 4; i++) { float d = v[i] - mean; sq += d * d; }
    sq = block_reduce_sum(sq, sh);
    const float rstd = rsqrtf(sq * (1.0f / DD) + 1e-5f);
    float* yr = y + (size_t)row * DD;
    #pragma unroll
    for (int i = 0; i < 4; i++) {
        int c = threadIdx.x + 256 * i;
        yr[c] = (v[i] - mean) * rstd * g[c] + b[c];
    }
}

// ---------------------------------------------------------------------------
// TF32 tensor-core GEMM: C[M,N] = A[M,K] @ B[K,N] + bias (+ epilogue)
// Block tile 128x128, K-tile 32, 256 threads (8 warps, 2x4 grid of 64x32
// warp tiles). cp.async double-buffered smem. mma.sync m16n8k8 tf32.
// EPI: 0 = none, 1 = exact GELU, 2 = residual add
// ---------------------------------------------------------------------------
#define AS_STRIDE 36     // 32 + 4 pad  (conflict-free fragment reads)
#define BS_STRIDE 136    // 128 + 8 pad
#define AS_FLOATS (128 * AS_STRIDE)   // 4608
#define BS_FLOATS (32 * BS_STRIDE)    // 4352
#define GEMM_SMEM_BYTES ((2 * AS_FLOATS + 2 * BS_FLOATS) * 4)  // 71680

template<int EPI>
__global__ void __launch_bounds__(256) gemm_tf32_kernel(
        const float* __restrict__ A, const float* __restrict__ B,
        const float* __restrict__ bias, const float* __restrict__ resid,
        float* __restrict__ C, int M, int N, int K) {
    extern __shared__ float smem[];
    float* AsBuf[2] = { smem, smem + AS_FLOATS };
    float* BsBuf[2] = { smem + 2 * AS_FLOATS, smem + 2 * AS_FLOATS + BS_FLOATS };

    const int bm = blockIdx.y * 128;
    const int bn = blockIdx.x * 128;
    const int tid  = threadIdx.x;
    const int warp = tid >> 5;
    const int lane = tid & 31;
    const int g    = lane >> 2;   // group id 0..7
    const int tig  = lane & 3;    // thread-in-group 0..3
    const int warp_m = (warp & 1) * 64;
    const int warp_n = (warp >> 1) * 32;

    float acc[4][4][4];
    #pragma unroll
    for (int mf = 0; mf < 4; mf++)
        #pragma unroll
        for (int nf = 0; nf < 4; nf++)
            #pragma unroll
            for (int r = 0; r < 4; r++) acc[mf][nf][r] = 0.0f;

    const int NK = K >> 5;  // K / 32

    // ---- tile loader (cp.async, 4+4 float4 per thread) ----
    auto load_tile = [&](int k0, int buf) {
        float* As = AsBuf[buf];
        float* Bs = BsBuf[buf];
        #pragma unroll
        for (int i = 0; i < 4; i++) {
            int f = tid + 256 * i;
            int row = f >> 3, c4 = (f & 7) << 2;
            cp_async16(&As[row * AS_STRIDE + c4],
                       A + (size_t)(bm + row) * K + k0 + c4);
        }
        #pragma unroll
        for (int i = 0; i < 4; i++) {
            int f = tid + 256 * i;
            int row = f >> 5, c4 = (f & 31) << 2;
            cp_async16(&Bs[row * BS_STRIDE + c4],
                       B + (size_t)(k0 + row) * N + bn + c4);
        }
        cp_async_commit();
    };

    load_tile(0, 0);

    for (int kt = 0; kt < NK; kt++) {
        if (kt + 1 < NK) {
            load_tile((kt + 1) << 5, (kt + 1) & 1);
            cp_async_wait<1>();
        } else {
            cp_async_wait<0>();
        }
        __syncthreads();

        const float* As = AsBuf[kt & 1];
        const float* Bs = BsBuf[kt & 1];

        #pragma unroll
        for (int ks = 0; ks < 4; ks++) {
            const int kk = ks << 3;
            uint32_t afrag[4][4], bfrag[4][2];
            #pragma unroll
            for (int mf = 0; mf < 4; mf++) {
                const int r0 = warp_m + mf * 16 + g;
                afrag[mf][0] = f2tf32(As[(r0    ) * AS_STRIDE + kk + tig    ]);
                afrag[mf][1] = f2tf32(As[(r0 + 8) * AS_STRIDE + kk + tig    ]);
                afrag[mf][2] = f2tf32(As[(r0    ) * AS_STRIDE + kk + tig + 4]);
                afrag[mf][3] = f2tf32(As[(r0 + 8) * AS_STRIDE + kk + tig + 4]);
            }
            #pragma unroll
            for (int nf = 0; nf < 4; nf++) {
                const int c0 = warp_n + nf * 8 + g;
                bfrag[nf][0] = f2tf32(Bs[(kk + tig    ) * BS_STRIDE + c0]);
                bfrag[nf][1] = f2tf32(Bs[(kk + tig + 4) * BS_STRIDE + c0]);
            }
            #pragma unroll
            for (int mf = 0; mf < 4; mf++)
                #pragma unroll
                for (int nf = 0; nf < 4; nf++)
                    mma_tf32(acc[mf][nf], afrag[mf], bfrag[nf]);
        }
        __syncthreads();
    }

    // ---- epilogue ----
    #pragma unroll
    for (int mf = 0; mf < 4; mf++) {
        #pragma unroll
        for (int nf = 0; nf < 4; nf++) {
            const int row0 = bm + warp_m + mf * 16 + g;
            const int row1 = row0 + 8;
            const int col  = bn + warp_n + nf * 8 + 2 * tig;
            const float b0 = bias[col], b1 = bias[col + 1];
            float v0 = acc[mf][nf][0] + b0;
            float v1 = acc[mf][nf][1] + b1;
            float v2 = acc[mf][nf][2] + b0;
            float v3 = acc[mf][nf][3] + b1;
            if (EPI == 1) {
                v0 = gelu_exact(v0); v1 = gelu_exact(v1);
                v2 = gelu_exact(v2); v3 = gelu_exact(v3);
            }
            if (EPI == 2) {
                float2 r0v = *(const float2*)(resid + (size_t)row0 * N + col);
                float2 r1v = *(const float2*)(resid + (size_t)row1 * N + col);
                v0 += r0v.x; v1 += r0v.y; v2 += r1v.x; v3 += r1v.y;
            }
            *(float2*)(C + (size_t)row0 * N + col) = make_float2(v0, v1);
            *(float2*)(C + (size_t)row1 * N + col) = make_float2(v2, v3);
        }
    }
}

// ---------------------------------------------------------------------------
// Masked attention (flash-style, fp32, online softmax) — unchanged from R1
// ---------------------------------------------------------------------------
__global__ void __launch_bounds__(256) attn_kernel(
        const float* __restrict__ Q, const float* __restrict__ K,
        const float* __restrict__ V, float* __restrict__ O) {
    __shared__ float Qs[16][65];
    __shared__ float Ks[64][64];
    __shared__ float Vs[64][64];
    __shared__ float Ss[16][65];
    __shared__ float mS[16], lS[16], scS[16];

    const int qc = blockIdx.x;
    const int h  = blockIdx.y;
    const int b  = blockIdx.z;
    const int qbase = qc * 16;
    const int tid = threadIdx.x;

    for (int e = tid; e < 16 * 64; e += 256) {
        int qi = e >> 6, d = e & 63;
        Qs[qi][d] = Q[(size_t)(b * SS + qbase + qi) * DD + h * DKK + d] * 0.125f;
    }
    if (tid < 16) { mS[tid] = -INFINITY; lS[tid] = 0.0f; }

    const int oq = tid & 15;
    const int og = tid >> 4;
    const int sq = tid & 15;
    const int sg = tid >> 4;
    float acc[4] = {0.f, 0.f, 0.f, 0.f};

    __syncthreads();

    for (int c = 0; c < SS / 64; c++) {
        bool use = (c == 0) || (qbase < NGLOBAL) ||
                   (64 * c + 63 >= qbase - WINDOW && 64 * c <= qbase + 15 + WINDOW);
        if (!use) continue;

        __syncthreads();
        for (int e = tid; e < 64 * 64; e += 256) {
            int r = e >> 6, d = e & 63;
            size_t gi = (size_t)(b * SS + 64 * c + r) * DD + h * DKK + d;
            Ks[r][d] = K[gi];
            Vs[r][d] = V[gi];
        }
        __syncthreads();

        const int i = qbase + sq;
        #pragma unroll
        for (int kk = 0; kk < 4; kk++) {
            const int kr = sg * 4 + kk;
            const int j = 64 * c + kr;
            const bool ok = (abs(i - j) <= WINDOW) || (i < NGLOBAL) || (j < NGLOBAL);
            float s = -INFINITY;
            if (ok) {
                s = 0.0f;
                #pragma unroll
                for (int d = 0; d < 64; d++) s += Qs[sq][d] * Ks[kr][d];
            }
            Ss[sq][kr] = s;
        }
        __syncthreads();

        if (tid < 16) {
            float mx = mS[tid];
            #pragma unroll 8
            for (int k2 = 0; k2 < 64; k2++) mx = fmaxf(mx, Ss[tid][k2]);
            const float sc = expf(mS[tid] - mx);
            float l = lS[tid] * sc;
            #pragma unroll 8
            for (int k2 = 0; k2 < 64; k2++) {
                float p = expf(Ss[tid][k2] - mx);
                Ss[tid][k2] = p;
                l += p;
            }
            mS[tid] = mx; lS[tid] = l; scS[tid] = sc;
        }
        __syncthreads();

        const float sc = scS[oq];
        #pragma unroll
        for (int dd = 0; dd < 4; dd++) acc[dd] *= sc;
        #pragma unroll 8
        for (int k2 = 0; k2 < 64; k2++) {
            const float p = Ss[oq][k2];
            #pragma unroll
            for (int dd = 0; dd < 4; dd++)
                acc[dd] += p * Vs[k2][og * 4 + dd];
        }
    }

    const float inv = 1.0f / lS[oq];
    float* op = O + (size_t)(b * SS + qbase + oq) * DD + h * DKK + og * 4;
    #pragma unroll
    for (int dd = 0; dd < 4; dd++) op[dd] = acc[dd] * inv;
}

// ---------------------------------------------------------------------------
// Launch
// ---------------------------------------------------------------------------
extern "C" void kernel_launch(void* const* d_in, const int* in_sizes, int n_in,
                              void* d_out, int out_size) {
    const float* x     = (const float*)d_in[0];
    const float* Wq    = (const float*)d_in[1];
    const float* bq    = (const float*)d_in[2];
    const float* Wk    = (const float*)d_in[3];
    const float* bk    = (const float*)d_in[4];
    const float* Wv    = (const float*)d_in[5];
    const float* bv    = (const float*)d_in[6];
    const float* Wo    = (const float*)d_in[7];
    const float* bo    = (const float*)d_in[8];
    const float* ln1_g = (const float*)d_in[9];
    const float* ln1_b = (const float*)d_in[10];
    const float* W1    = (const float*)d_in[11];
    const float* b1    = (const float*)d_in[12];
    const float* W2    = (const float*)d_in[13];
    const float* b2    = (const float*)d_in[14];
    const float* ln2_g = (const float*)d_in[15];
    const float* ln2_b = (const float*)d_in[16];
    float* out = (float*)d_out;

    float *xn, *q, *k, *v, *att, *x1, *xn2, *hbuf;
    cudaGetSymbolAddress((void**)&xn,   g_xn);
    cudaGetSymbolAddress((void**)&q,    g_q);
    cudaGetSymbolAddress((void**)&k,    g_k);
    cudaGetSymbolAddress((void**)&v,    g_v);
    cudaGetSymbolAddress((void**)&att,  g_att);
    cudaGetSymbolAddress((void**)&x1,   g_x1);
    cudaGetSymbolAddress((void**)&xn2,  g_xn2);
    cudaGetSymbolAddress((void**)&hbuf, g_h);

    cudaFuncSetAttribute(gemm_tf32_kernel<0>,
        cudaFuncAttributeMaxDynamicSharedMemorySize, GEMM_SMEM_BYTES);
    cudaFuncSetAttribute(gemm_tf32_kernel<1>,
        cudaFuncAttributeMaxDynamicSharedMemorySize, GEMM_SMEM_BYTES);
    cudaFuncSetAttribute(gemm_tf32_kernel<2>,
        cudaFuncAttributeMaxDynamicSharedMemorySize, GEMM_SMEM_BYTES);

    // 1) xn = LN(x)
    ln_kernel<<<MM, 256>>>(x, ln1_g, ln1_b, xn);

    // 2) q,k,v = xn @ W{q,k,v} + b
    dim3 g1(DD / 128, MM / 128);
    gemm_tf32_kernel<0><<<g1, 256, GEMM_SMEM_BYTES>>>(xn, Wq, bq, nullptr, q, MM, DD, DD);
    gemm_tf32_kernel<0><<<g1, 256, GEMM_SMEM_BYTES>>>(xn, Wk, bk, nullptr, k, MM, DD, DD);
    gemm_tf32_kernel<0><<<g1, 256, GEMM_SMEM_BYTES>>>(xn, Wv, bv, nullptr, v, MM, DD, DD);

    // 3) masked attention
    attn_kernel<<<dim3(SS / 16, HH, BB), 256>>>(q, k, v, att);

    // 4) x1 = x + att @ Wo + bo
    gemm_tf32_kernel<2><<<g1, 256, GEMM_SMEM_BYTES>>>(att, Wo, bo, x, x1, MM, DD, DD);

    // 5) xn2 = LN(x1)
    ln_kernel<<<MM, 256>>>(x1, ln2_g, ln2_b, xn2);

    // 6) h = gelu(xn2 @ W1 + b1)
    dim3 g2(DFF / 128, MM / 128);
    gemm_tf32_kernel<1><<<g2, 256, GEMM_SMEM_BYTES>>>(xn2, W1, b1, nullptr, hbuf, MM, DFF, DD);

    // 7) out = x1 + h @ W2 + b2
    gemm_tf32_kernel<2><<<g1, 256, GEMM_SMEM_BYTES>>>(hbuf, W2, b2, x1, out, MM, DD, DFF);
}

// round 4
// speedup vs baseline: 2.2979x; 1.1981x over previous
#include <cuda_runtime.h>
#include <math.h>
#include <stdint.h>

// ---------------------------------------------------------------------------
// Problem constants
// ---------------------------------------------------------------------------
#define BB 2
#define SS 2048
#define DD 1024
#define HH 16
#define DKK 64
#define DFF 4096
#define WINDOW 128
#define NGLOBAL 16
#define MM (BB * SS)   // 4096 rows

// ---------------------------------------------------------------------------
// Scratch (device globals; no allocation allowed)
// ---------------------------------------------------------------------------
__device__ float g_xn  [MM * DD];
__device__ float g_qkv [MM * 3 * DD];
__device__ float g_att [MM * DD];
__device__ float g_x1  [MM * DD];
__device__ float g_xn2 [MM * DD];
__device__ float g_h   [MM * DFF];
__device__ float g_wqkv[DD * 3 * DD];
__device__ float g_wo  [DD * DD];
__device__ float g_w1  [DD * DFF];
__device__ float g_w2  [DFF * DD];
__device__ float g_bqkv[3 * DD];

// ---------------------------------------------------------------------------
// PTX helpers
// ---------------------------------------------------------------------------
__device__ __forceinline__ float round_tf32(float x) {
    uint32_t r;
    asm("cvt.rna.tf32.f32 %0, %1;" : "=r"(r) : "f"(x));
    return __uint_as_float(r);
}

__device__ __forceinline__ void mma_tf32(float c[4], const uint32_t a[4], const uint32_t b[2]) {
    asm volatile(
        "mma.sync.aligned.m16n8k8.row.col.f32.tf32.tf32.f32 "
        "{%0,%1,%2,%3}, {%4,%5,%6,%7}, {%8,%9}, {%0,%1,%2,%3};\n"
        : "+f"(c[0]), "+f"(c[1]), "+f"(c[2]), "+f"(c[3])
        : "r"(a[0]), "r"(a[1]), "r"(a[2]), "r"(a[3]), "r"(b[0]), "r"(b[1]));
}

__device__ __forceinline__ void cp_async16(float* smem_dst, const float* gmem_src) {
    uint32_t s = (uint32_t)__cvta_generic_to_shared(smem_dst);
    asm volatile("cp.async.cg.shared.global [%0], [%1], 16;\n" :: "r"(s), "l"(gmem_src));
}
__device__ __forceinline__ void cp_async_commit() {
    asm volatile("cp.async.commit_group;\n");
}
template<int N>
__device__ __forceinline__ void cp_async_wait() {
    asm volatile("cp.async.wait_group %0;\n" :: "n"(N));
}

__device__ __forceinline__ float gelu_exact(float x) {
    return 0.5f * x * (1.0f + erff(x * 0.70710678118654752f));
}

// ---------------------------------------------------------------------------
// Pre-round weights/bias to tf32 and place into (possibly strided) dst.
// dst[r*dstride + coff + c] = round_tf32(src[r*C + c])
// ---------------------------------------------------------------------------
__global__ void __launch_bounds__(256) round_copy_kernel(
        const float* __restrict__ src, float* __restrict__ dst,
        int total, int C, int dstride, int coff) {
    int idx = blockIdx.x * 256 + threadIdx.x;
    if (idx < total) {
        int r = idx / C, c = idx - r * C;
        dst[(size_t)r * dstride + coff + c] = round_tf32(src[idx]);
    }
}

// ---------------------------------------------------------------------------
// LayerNorm: one block per row of 1024, 256 threads. Output tf32-rounded.
// ---------------------------------------------------------------------------
__device__ __forceinline__ float block_reduce_sum(float v, float* sh) {
    int lane = threadIdx.x & 31;
    int wid  = threadIdx.x >> 5;
    #pragma unroll
    for (int o = 16; o > 0; o >>= 1) v += __shfl_down_sync(0xffffffffu, v, o);
    if (lane == 0) sh[wid] = v;
    __syncthreads();
    if (wid == 0) {
        float t = (lane < 8) ? sh[lane] : 0.0f;
        #pragma unroll
        for (int o = 4; o > 0; o >>= 1) t += __shfl_down_sync(0xffffffffu, t, o);
        if (lane == 0) sh[0] = t;
    }
    __syncthreads();
    float r = sh[0];
    __syncthreads();
    return r;
}

__global__ void __launch_bounds__(256) ln_kernel(const float* __restrict__ x,
                                                 const float* __restrict__ g,
                                                 const float* __restrict__ b,
                                                 float* __restrict__ y) {
    __shared__ float sh[32];
    const int row = blockIdx.x;
    const float* xr = x + (size_t)row * DD;
    float v[4];
    float s = 0.0f;
    #pragma unroll
    for (int i = 0; i < 4; i++) { v[i] = xr[threadIdx.x + 256 * i]; s += v[i]; }
    s = block_reduce_sum(s, sh);
    const float mean = s * (1.0f / DD);
    float sq = 0.0f;
    #pragma unroll
    for (int i = 0; i < 4; i++) { float d = v[i] - mean; sq += d * d; }
    sq = block_reduce_sum(sq, sh);
    const float rstd = rsqrtf(sq * (1.0f / DD) + 1e-5f);
    float* yr = y + (size_t)row * DD;
    #pragma unroll
    for (int i = 0; i < 4; i++) {
        int c = threadIdx.x + 256 * i;
        yr[c] = round_tf32((v[i] - mean) * rstd * g[c] + b[c]);
    }
}

// ---------------------------------------------------------------------------
// TF32 tensor-core GEMM: C[M,N] = A[M,K] @ B[K,N] + bias (+ epilogue)
// Inputs MUST be pre-rounded to tf32 (no CVT in mainloop).
// Block tile 128x128, K-tile 32, 256 threads (8 warps, 2x4 of 64x32 warp
// tiles). cp.async double-buffered smem. 2 CTAs/SM via launch_bounds.
// EPI: 0 = none, 1 = exact GELU (tf32-rounded output), 2 = residual add
// ---------------------------------------------------------------------------
#define AS_STRIDE 36
#define BS_STRIDE 136
#define AS_FLOATS (128 * AS_STRIDE)   // 4608
#define BS_FLOATS (32 * BS_STRIDE)    // 4352
#define GEMM_SMEM_BYTES ((2 * AS_FLOATS + 2 * BS_FLOATS) * 4)  // 71680

template<int EPI>
__global__ void __launch_bounds__(256, 2) gemm_tf32_kernel(
        const float* __restrict__ A, const float* __restrict__ B,
        const float* __restrict__ bias, const float* __restrict__ resid,
        float* __restrict__ C, int M, int N, int K) {
    extern __shared__ float smem[];
    float* AsBuf[2] = { smem, smem + AS_FLOATS };
    float* BsBuf[2] = { smem + 2 * AS_FLOATS, smem + 2 * AS_FLOATS + BS_FLOATS };

    const int bm = blockIdx.y * 128;
    const int bn = blockIdx.x * 128;
    const int tid  = threadIdx.x;
    const int warp = tid >> 5;
    const int lane = tid & 31;
    const int g    = lane >> 2;   // 0..7
    const int tig  = lane & 3;    // 0..3
    const int warp_m = (warp & 1) * 64;
    const int warp_n = (warp >> 1) * 32;

    float acc[4][4][4];
    #pragma unroll
    for (int mf = 0; mf < 4; mf++)
        #pragma unroll
        for (int nf = 0; nf < 4; nf++)
            #pragma unroll
            for (int r = 0; r < 4; r++) acc[mf][nf][r] = 0.0f;

    const int NK = K >> 5;

    auto load_tile = [&](int k0, int buf) {
        float* As = AsBuf[buf];
        float* Bs = BsBuf[buf];
        #pragma unroll
        for (int i = 0; i < 4; i++) {
            int f = tid + 256 * i;
            int row = f >> 3, c4 = (f & 7) << 2;
            cp_async16(&As[row * AS_STRIDE + c4],
                       A + (size_t)(bm + row) * K + k0 + c4);
        }
        #pragma unroll
        for (int i = 0; i < 4; i++) {
            int f = tid + 256 * i;
            int row = f >> 5, c4 = (f & 31) << 2;
            cp_async16(&Bs[row * BS_STRIDE + c4],
                       B + (size_t)(k0 + row) * N + bn + c4);
        }
        cp_async_commit();
    };

    load_tile(0, 0);

    for (int kt = 0; kt < NK; kt++) {
        if (kt + 1 < NK) {
            load_tile((kt + 1) << 5, (kt + 1) & 1);
            cp_async_wait<1>();
        } else {
            cp_async_wait<0>();
        }
        __syncthreads();

        const float* As = AsBuf[kt & 1];
        const float* Bs = BsBuf[kt & 1];

        #pragma unroll
        for (int ks = 0; ks < 4; ks++) {
            const int kk = ks << 3;
            uint32_t afrag[4][4], bfrag[4][2];
            #pragma unroll
            for (int mf = 0; mf < 4; mf++) {
                const int r0 = warp_m + mf * 16 + g;
                afrag[mf][0] = __float_as_uint(As[(r0    ) * AS_STRIDE + kk + tig    ]);
                afrag[mf][1] = __float_as_uint(As[(r0 + 8) * AS_STRIDE + kk + tig    ]);
                afrag[mf][2] = __float_as_uint(As[(r0    ) * AS_STRIDE + kk + tig + 4]);
                afrag[mf][3] = __float_as_uint(As[(r0 + 8) * AS_STRIDE + kk + tig + 4]);
            }
            #pragma unroll
            for (int nf = 0; nf < 4; nf++) {
                const int c0 = warp_n + nf * 8 + g;
                bfrag[nf][0] = __float_as_uint(Bs[(kk + tig    ) * BS_STRIDE + c0]);
                bfrag[nf][1] = __float_as_uint(Bs[(kk + tig + 4) * BS_STRIDE + c0]);
            }
            #pragma unroll
            for (int mf = 0; mf < 4; mf++)
                #pragma unroll
                for (int nf = 0; nf < 4; nf++)
                    mma_tf32(acc[mf][nf], afrag[mf], bfrag[nf]);
        }
        __syncthreads();
    }

    // ---- epilogue ----
    #pragma unroll
    for (int mf = 0; mf < 4; mf++) {
        #pragma unroll
        for (int nf = 0; nf < 4; nf++) {
            const int row0 = bm + warp_m + mf * 16 + g;
            const int row1 = row0 + 8;
            const int col  = bn + warp_n + nf * 8 + 2 * tig;
            const float b0 = bias[col], b1 = bias[col + 1];
            float v0 = acc[mf][nf][0] + b0;
            float v1 = acc[mf][nf][1] + b1;
            float v2 = acc[mf][nf][2] + b0;
            float v3 = acc[mf][nf][3] + b1;
            if (EPI == 1) {
                v0 = round_tf32(gelu_exact(v0)); v1 = round_tf32(gelu_exact(v1));
                v2 = round_tf32(gelu_exact(v2)); v3 = round_tf32(gelu_exact(v3));
            }
            if (EPI == 2) {
                float2 r0v = *(const float2*)(resid + (size_t)row0 * N + col);
                float2 r1v = *(const float2*)(resid + (size_t)row1 * N + col);
                v0 += r0v.x; v1 += r0v.y; v2 += r1v.x; v3 += r1v.y;
            }
            *(float2*)(C + (size_t)row0 * N + col) = make_float2(v0, v1);
            *(float2*)(C + (size_t)row1 * N + col) = make_float2(v2, v3);
        }
    }
}

// ---------------------------------------------------------------------------
// Masked attention (flash-style, fp32, parallel online softmax).
// Q/K/V live in the fused qkv buffer: row stride 3*DD, col offsets 0/DD/2*DD.
// Output tf32-rounded (feeds the Wo GEMM).
// ---------------------------------------------------------------------------
__global__ void __launch_bounds__(256) attn_kernel(
        const float* __restrict__ QKV, float* __restrict__ O) {
    __shared__ float Qs[16][65];
    __shared__ float Ks[64][64];
    __shared__ float Vs[64][64];
    __shared__ float Ss[16][65];
    __shared__ float red[16][17];
    __shared__ float mS[16], lS[16], scS[16];

    const int qc = blockIdx.x;
    const int h  = blockIdx.y;
    const int b  = blockIdx.z;
    const int qbase = qc * 16;
    const int tid = threadIdx.x;
    const int RS = 3 * DD;

    for (int e = tid; e < 16 * 64; e += 256) {
        int qi = e >> 6, d = e & 63;
        Qs[qi][d] = QKV[(size_t)(b * SS + qbase + qi) * RS + h * DKK + d] * 0.125f;
    }
    if (tid < 16) { mS[tid] = -INFINITY; lS[tid] = 0.0f; }

    const int oq = tid & 15;
    const int og = tid >> 4;
    const int sq = tid & 15;
    const int sg = tid >> 4;
    float acc[4] = {0.f, 0.f, 0.f, 0.f};

    __syncthreads();

    for (int c = 0; c < SS / 64; c++) {
        bool use = (c == 0) || (qbase < NGLOBAL) ||
                   (64 * c + 63 >= qbase - WINDOW && 64 * c <= qbase + 15 + WINDOW);
        if (!use) continue;

        __syncthreads();
        for (int e = tid; e < 64 * 64; e += 256) {
            int r = e >> 6, d = e & 63;
            size_t gi = (size_t)(b * SS + 64 * c + r) * RS + h * DKK + d;
            Ks[r][d] = QKV[gi + DD];
            Vs[r][d] = QKV[gi + 2 * DD];
        }
        __syncthreads();

        const int i = qbase + sq;
        float sv[4];
        float pmax = -INFINITY;
        #pragma unroll
        for (int kk = 0; kk < 4; kk++) {
            const int kr = sg * 4 + kk;
            const int j = 64 * c + kr;
            const bool ok = (abs(i - j) <= WINDOW) || (i < NGLOBAL) || (j < NGLOBAL);
            float s = -INFINITY;
            if (ok) {
                s = 0.0f;
                #pragma unroll
                for (int d = 0; d < 64; d++) s += Qs[sq][d] * Ks[kr][d];
            }
            sv[kk] = s;
            pmax = fmaxf(pmax, s);
        }
        red[sq][sg] = pmax;
        __syncthreads();

        if (tid < 16) {
            float mx = mS[tid];
            #pragma unroll
            for (int g2 = 0; g2 < 16; g2++) mx = fmaxf(mx, red[tid][g2]);
            scS[tid] = expf(mS[tid] - mx);
            mS[tid]  = mx;
        }
        __syncthreads();

        const float mx = mS[sq];
        float ps = 0.0f;
        #pragma unroll
        for (int kk = 0; kk < 4; kk++) {
            float p = expf(sv[kk] - mx);
            Ss[sq][sg * 4 + kk] = p;
            ps += p;
        }
        red[sq][sg] = ps;
        __syncthreads();

        if (tid < 16) {
            float l = lS[tid] * scS[tid];
            #pragma unroll
            for (int g2 = 0; g2 < 16; g2++) l += red[tid][g2];
            lS[tid] = l;
        }
        __syncthreads();

        const float sc = scS[oq];
        #pragma unroll
        for (int dd = 0; dd < 4; dd++) acc[dd] *= sc;
        #pragma unroll 8
        for (int k2 = 0; k2 < 64; k2++) {
            const float p = Ss[oq][k2];
            #pragma unroll
            for (int dd = 0; dd < 4; dd++)
                acc[dd] += p * Vs[k2][og * 4 + dd];
        }
    }

    const float inv = 1.0f / lS[oq];
    float* op = O + (size_t)(b * SS + qbase + oq) * DD + h * DKK + og * 4;
    #pragma unroll
    for (int dd = 0; dd < 4; dd++) op[dd] = round_tf32(acc[dd] * inv);
}

// ---------------------------------------------------------------------------
// Launch
// ---------------------------------------------------------------------------
extern "C" void kernel_launch(void* const* d_in, const int* in_sizes, int n_in,
                              void* d_out, int out_size) {
    const float* x     = (const float*)d_in[0];
    const float* Wq    = (const float*)d_in[1];
    const float* bq    = (const float*)d_in[2];
    const float* Wk    = (const float*)d_in[3];
    const float* bk    = (const float*)d_in[4];
    const float* Wv    = (const float*)d_in[5];
    const float* bv    = (const float*)d_in[6];
    const float* Wo    = (const float*)d_in[7];
    const float* bo    = (const float*)d_in[8];
    const float* ln1_g = (const float*)d_in[9];
    const float* ln1_b = (const float*)d_in[10];
    const float* W1    = (const float*)d_in[11];
    const float* b1    = (const float*)d_in[12];
    const float* W2    = (const float*)d_in[13];
    const float* b2    = (const float*)d_in[14];
    const float* ln2_g = (const float*)d_in[15];
    const float* ln2_b = (const float*)d_in[16];
    float* out = (float*)d_out;

    float *xn, *qkv, *att, *x1, *xn2, *hbuf, *wqkv, *wo, *w1, *w2, *bqkv;
    cudaGetSymbolAddress((void**)&xn,   g_xn);
    cudaGetSymbolAddress((void**)&qkv,  g_qkv);
    cudaGetSymbolAddress((void**)&att,  g_att);
    cudaGetSymbolAddress((void**)&x1,   g_x1);
    cudaGetSymbolAddress((void**)&xn2,  g_xn2);
    cudaGetSymbolAddress((void**)&hbuf, g_h);
    cudaGetSymbolAddress((void**)&wqkv, g_wqkv);
    cudaGetSymbolAddress((void**)&wo,   g_wo);
    cudaGetSymbolAddress((void**)&w1,   g_w1);
    cudaGetSymbolAddress((void**)&w2,   g_w2);
    cudaGetSymbolAddress((void**)&bqkv, g_bqkv);

    cudaFuncSetAttribute(gemm_tf32_kernel<0>,
        cudaFuncAttributeMaxDynamicSharedMemorySize, GEMM_SMEM_BYTES);
    cudaFuncSetAttribute(gemm_tf32_kernel<1>,
        cudaFuncAttributeMaxDynamicSharedMemorySize, GEMM_SMEM_BYTES);
    cudaFuncSetAttribute(gemm_tf32_kernel<2>,
        cudaFuncAttributeMaxDynamicSharedMemorySize, GEMM_SMEM_BYTES);

    // ---- pre-round weights to tf32 (fused QKV weight + bias concat) ----
    const int WB = (DD * DD + 255) / 256;
    round_copy_kernel<<<WB, 256>>>(Wq, wqkv, DD * DD, DD, 3 * DD, 0);
    round_copy_kernel<<<WB, 256>>>(Wk, wqkv, DD * DD, DD, 3 * DD, DD);
    round_copy_kernel<<<WB, 256>>>(Wv, wqkv, DD * DD, DD, 3 * DD, 2 * DD);
    round_copy_kernel<<<WB, 256>>>(Wo, wo,   DD * DD, DD, DD, 0);
    round_copy_kernel<<<(DD * DFF + 255) / 256, 256>>>(W1, w1, DD * DFF, DFF, DFF, 0);
    round_copy_kernel<<<(DFF * DD + 255) / 256, 256>>>(W2, w2, DFF * DD, DD, DD, 0);
    round_copy_kernel<<<(DD + 255) / 256, 256>>>(bq, bqkv, DD, DD, 3 * DD, 0);
    round_copy_kernel<<<(DD + 255) / 256, 256>>>(bk, bqkv, DD, DD, 3 * DD, DD);
    round_copy_kernel<<<(DD + 255) / 256, 256>>>(bv, bqkv, DD, DD, 3 * DD, 2 * DD);

    // 1) xn = LN(x)   (tf32-rounded)
    ln_kernel<<<MM, 256>>>(x, ln1_g, ln1_b, xn);

    // 2) qkv = xn @ Wqkv + bqkv   (one fused GEMM, N=3072)
    dim3 gq(3 * DD / 128, MM / 128);
    gemm_tf32_kernel<0><<<gq, 256, GEMM_SMEM_BYTES>>>(xn, wqkv, bqkv, nullptr,
                                                      qkv, MM, 3 * DD, DD);

    // 3) masked attention (tf32-rounded output)
    attn_kernel<<<dim3(SS / 16, HH, BB), 256>>>(qkv, att);

    // 4) x1 = x + att @ Wo + bo
    dim3 g1(DD / 128, MM / 128);
    gemm_tf32_kernel<2><<<g1, 256, GEMM_SMEM_BYTES>>>(att, wo, bo, x, x1, MM, DD, DD);

    // 5) xn2 = LN(x1)  (tf32-rounded)
    ln_kernel<<<MM, 256>>>(x1, ln2_g, ln2_b, xn2);

    // 6) h = gelu(xn2 @ W1 + b1)  (tf32-rounded)
    dim3 g2(DFF / 128, MM / 128);
    gemm_tf32_kernel<1><<<g2, 256, GEMM_SMEM_BYTES>>>(xn2, w1, b1, nullptr, hbuf, MM, DFF, DD);

    // 7) out = x1 + h @ W2 + b2
    gemm_tf32_kernel<2><<<g1, 256, GEMM_SMEM_BYTES>>>(hbuf, w2, b2, x1, out, MM, DD, DFF);
}

// round 5
// speedup vs baseline: 2.7008x; 1.1753x over previous
#include <cuda_runtime.h>
#include <math.h>
#include <stdint.h>

// ---------------------------------------------------------------------------
// Problem constants
// ---------------------------------------------------------------------------
#define BB 2
#define SS 2048
#define DD 1024
#define HH 16
#define DKK 64
#define DFF 4096
#define WINDOW 128
#define NGLOBAL 16
#define MM (BB * SS)   // 4096 rows

// ---------------------------------------------------------------------------
// Scratch (device globals; no allocation allowed)
// ---------------------------------------------------------------------------
__device__ float g_xn  [MM * DD];
__device__ float g_qkv [MM * 3 * DD];
__device__ float g_att [MM * DD];
__device__ float g_x1  [MM * DD];
__device__ float g_xn2 [MM * DD];
__device__ float g_h   [MM * DFF];
__device__ float g_wqkv[DD * 3 * DD];
__device__ float g_wo  [DD * DD];
__device__ float g_w1  [DD * DFF];
__device__ float g_w2  [DFF * DD];
__device__ float g_bqkv[3 * DD];

// ---------------------------------------------------------------------------
// PTX helpers
// ---------------------------------------------------------------------------
__device__ __forceinline__ float round_tf32(float x) {
    uint32_t r;
    asm("cvt.rna.tf32.f32 %0, %1;" : "=r"(r) : "f"(x));
    return __uint_as_float(r);
}
__device__ __forceinline__ float4 rtf4(float4 v) {
    v.x = round_tf32(v.x); v.y = round_tf32(v.y);
    v.z = round_tf32(v.z); v.w = round_tf32(v.w);
    return v;
}

__device__ __forceinline__ void mma_tf32(float c[4], const uint32_t a[4], const uint32_t b[2]) {
    asm volatile(
        "mma.sync.aligned.m16n8k8.row.col.f32.tf32.tf32.f32 "
        "{%0,%1,%2,%3}, {%4,%5,%6,%7}, {%8,%9}, {%0,%1,%2,%3};\n"
        : "+f"(c[0]), "+f"(c[1]), "+f"(c[2]), "+f"(c[3])
        : "r"(a[0]), "r"(a[1]), "r"(a[2]), "r"(a[3]), "r"(b[0]), "r"(b[1]));
}

__device__ __forceinline__ void cp_async16(float* smem_dst, const float* gmem_src) {
    uint32_t s = (uint32_t)__cvta_generic_to_shared(smem_dst);
    asm volatile("cp.async.cg.shared.global [%0], [%1], 16;\n" :: "r"(s), "l"(gmem_src));
}
__device__ __forceinline__ void cp_async_commit() {
    asm volatile("cp.async.commit_group;\n");
}
template<int N>
__device__ __forceinline__ void cp_async_wait() {
    asm volatile("cp.async.wait_group %0;\n" :: "n"(N));
}

__device__ __forceinline__ float gelu_exact(float x) {
    return 0.5f * x * (1.0f + erff(x * 0.70710678118654752f));
}

// ---------------------------------------------------------------------------
// Fused prepass: round weights to tf32 into staging buffers (float4), concat
// QKV weights + biases. One launch.
// f4 segment layout:
//   [0, 786432)          Wq|Wk|Wv -> wqkv (interleaved cols, 3*1024 wide)
//   [786432, 1048576)    Wo
//   [1048576, 2097152)   W1
//   [2097152, 3145728)   W2
//   [3145728, 3146496)   bq|bk|bv -> bqkv
// ---------------------------------------------------------------------------
#define PREP_TOTAL 3146496
__global__ void __launch_bounds__(256) prep_kernel(
        const float4* __restrict__ Wq, const float4* __restrict__ Wk,
        const float4* __restrict__ Wv, const float4* __restrict__ Wo,
        const float4* __restrict__ W1, const float4* __restrict__ W2,
        const float4* __restrict__ bq, const float4* __restrict__ bk,
        const float4* __restrict__ bv,
        float4* __restrict__ wqkv, float4* __restrict__ wo,
        float4* __restrict__ w1, float4* __restrict__ w2,
        float4* __restrict__ bqkv) {
    int idx = blockIdx.x * 256 + threadIdx.x;
    if (idx < 786432) {
        int sub = idx >> 18;            // 0..2
        int k   = idx & 262143;
        int r   = k >> 8, c = k & 255;
        const float4* src = (sub == 0) ? Wq : (sub == 1) ? Wk : Wv;
        wqkv[r * 768 + sub * 256 + c] = rtf4(src[k]);
    } else if (idx < 1048576) {
        int k = idx - 786432;
        wo[k] = rtf4(Wo[k]);
    } else if (idx < 2097152) {
        int k = idx - 1048576;
        w1[k] = rtf4(W1[k]);
    } else if (idx < 3145728) {
        int k = idx - 2097152;
        w2[k] = rtf4(W2[k]);
    } else if (idx < PREP_TOTAL) {
        int k = idx - 3145728;          // 0..767
        int sub = k >> 8, c = k & 255;
        const float4* src = (sub == 0) ? bq : (sub == 1) ? bk : bv;
        bqkv[sub * 256 + c] = src[c];
    }
}

// ---------------------------------------------------------------------------
// LayerNorm: one block per row of 1024, 256 threads. Output tf32-rounded.
// ---------------------------------------------------------------------------
__device__ __forceinline__ float block_reduce_sum(float v, float* sh) {
    int lane = threadIdx.x & 31;
    int wid  = threadIdx.x >> 5;
    #pragma unroll
    for (int o = 16; o > 0; o >>= 1) v += __shfl_down_sync(0xffffffffu, v, o);
    if (lane == 0) sh[wid] = v;
    __syncthreads();
    if (wid == 0) {
        float t = (lane < 8) ? sh[lane] : 0.0f;
        #pragma unroll
        for (int o = 4; o > 0; o >>= 1) t += __shfl_down_sync(0xffffffffu, t, o);
        if (lane == 0) sh[0] = t;
    }
    __syncthreads();
    float r = sh[0];
    __syncthreads();
    return r;
}

__global__ void __launch_bounds__(256) ln_kernel(const float* __restrict__ x,
                                                 const float* __restrict__ g,
                                                 const float* __restrict__ b,
                                                 float* __restrict__ y) {
    __shared__ float sh[32];
    const int row = blockIdx.x;
    const float* xr = x + (size_t)row * DD;
    float v[4];
    float s = 0.0f;
    #pragma unroll
    for (int i = 0; i < 4; i++) { v[i] = xr[threadIdx.x + 256 * i]; s += v[i]; }
    s = block_reduce_sum(s, sh);
    const float mean = s * (1.0f / DD);
    float sq = 0.0f;
    #pragma unroll
    for (int i = 0; i < 4; i++) { float d = v[i] - mean; sq += d * d; }
    sq = block_reduce_sum(sq, sh);
    const float rstd = rsqrtf(sq * (1.0f / DD) + 1e-5f);
    float* yr = y + (size_t)row * DD;
    #pragma unroll
    for (int i = 0; i < 4; i++) {
        int c = threadIdx.x + 256 * i;
        yr[c] = round_tf32((v[i] - mean) * rstd * g[c] + b[c]);
    }
}

// ---------------------------------------------------------------------------
// TF32 tensor-core GEMM: C[M,N] = A[M,K] @ B[K,N] + bias (+ epilogue)
// Inputs pre-rounded to tf32. 128x128 CTA tile, 32-K tile, 256 threads
// (8 warps, 2x4 of 64x32 warp tiles). 3-stage cp.async ring, ONE
// __syncthreads per K-tile. 2 CTAs/SM.
// EPI: 0 = none, 1 = exact GELU (tf32-rounded output), 2 = residual add
// ---------------------------------------------------------------------------
#define AS_STRIDE 36
#define BS_STRIDE 136
#define AS_FLOATS (128 * AS_STRIDE)   // 4608
#define BS_FLOATS (32 * BS_STRIDE)    // 4352
#define STG_FLOATS (AS_FLOATS + BS_FLOATS)            // 8960
#define GEMM_SMEM_BYTES (3 * STG_FLOATS * 4)          // 107520

template<int EPI>
__global__ void __launch_bounds__(256, 2) gemm_tf32_kernel(
        const float* __restrict__ A, const float* __restrict__ B,
        const float* __restrict__ bias, const float* __restrict__ resid,
        float* __restrict__ C, int M, int N, int K) {
    extern __shared__ float smem[];

    const int bm = blockIdx.y * 128;
    const int bn = blockIdx.x * 128;
    const int tid  = threadIdx.x;
    const int warp = tid >> 5;
    const int lane = tid & 31;
    const int g    = lane >> 2;
    const int tig  = lane & 3;
    const int warp_m = (warp & 1) * 64;
    const int warp_n = (warp >> 1) * 32;

    float acc[4][4][4];
    #pragma unroll
    for (int mf = 0; mf < 4; mf++)
        #pragma unroll
        for (int nf = 0; nf < 4; nf++)
            #pragma unroll
            for (int r = 0; r < 4; r++) acc[mf][nf][r] = 0.0f;

    const int NK = K >> 5;

    auto load_tile = [&](int kt) {
        float* As = smem + (kt % 3) * STG_FLOATS;
        float* Bs = As + AS_FLOATS;
        const int k0 = kt << 5;
        #pragma unroll
        for (int i = 0; i < 4; i++) {
            int f = tid + 256 * i;
            int row = f >> 3, c4 = (f & 7) << 2;
            cp_async16(&As[row * AS_STRIDE + c4],
                       A + (size_t)(bm + row) * K + k0 + c4);
        }
        #pragma unroll
        for (int i = 0; i < 4; i++) {
            int f = tid + 256 * i;
            int row = f >> 5, c4 = (f & 31) << 2;
            cp_async16(&Bs[row * BS_STRIDE + c4],
                       B + (size_t)(k0 + row) * N + bn + c4);
        }
        cp_async_commit();
    };

    load_tile(0);
    load_tile(1);

    for (int kt = 0; kt < NK; kt++) {
        if (kt + 1 < NK) cp_async_wait<1>();
        else             cp_async_wait<0>();
        __syncthreads();
        if (kt + 2 < NK) load_tile(kt + 2);

        const float* As = smem + (kt % 3) * STG_FLOATS;
        const float* Bs = As + AS_FLOATS;

        #pragma unroll
        for (int ks = 0; ks < 4; ks++) {
            const int kk = ks << 3;
            uint32_t afrag[4][4], bfrag[4][2];
            #pragma unroll
            for (int mf = 0; mf < 4; mf++) {
                const int r0 = warp_m + mf * 16 + g;
                afrag[mf][0] = __float_as_uint(As[(r0    ) * AS_STRIDE + kk + tig    ]);
                afrag[mf][1] = __float_as_uint(As[(r0 + 8) * AS_STRIDE + kk + tig    ]);
                afrag[mf][2] = __float_as_uint(As[(r0    ) * AS_STRIDE + kk + tig + 4]);
                afrag[mf][3] = __float_as_uint(As[(r0 + 8) * AS_STRIDE + kk + tig + 4]);
            }
            #pragma unroll
            for (int nf = 0; nf < 4; nf++) {
                const int c0 = warp_n + nf * 8 + g;
                bfrag[nf][0] = __float_as_uint(Bs[(kk + tig    ) * BS_STRIDE + c0]);
                bfrag[nf][1] = __float_as_uint(Bs[(kk + tig + 4) * BS_STRIDE + c0]);
            }
            #pragma unroll
            for (int mf = 0; mf < 4; mf++)
                #pragma unroll
                for (int nf = 0; nf < 4; nf++)
                    mma_tf32(acc[mf][nf], afrag[mf], bfrag[nf]);
        }
    }

    // ---- epilogue ----
    #pragma unroll
    for (int mf = 0; mf < 4; mf++) {
        #pragma unroll
        for (int nf = 0; nf < 4; nf++) {
            const int row0 = bm + warp_m + mf * 16 + g;
            const int row1 = row0 + 8;
            const int col  = bn + warp_n + nf * 8 + 2 * tig;
            const float b0 = bias[col], b1 = bias[col + 1];
            float v0 = acc[mf][nf][0] + b0;
            float v1 = acc[mf][nf][1] + b1;
            float v2 = acc[mf][nf][2] + b0;
            float v3 = acc[mf][nf][3] + b1;
            if (EPI == 1) {
                v0 = round_tf32(gelu_exact(v0)); v1 = round_tf32(gelu_exact(v1));
                v2 = round_tf32(gelu_exact(v2)); v3 = round_tf32(gelu_exact(v3));
            }
            if (EPI == 2) {
                float2 r0v = *(const float2*)(resid + (size_t)row0 * N + col);
                float2 r1v = *(const float2*)(resid + (size_t)row1 * N + col);
                v0 += r0v.x; v1 += r0v.y; v2 += r1v.x; v3 += r1v.y;
            }
            *(float2*)(C + (size_t)row0 * N + col) = make_float2(v0, v1);
            *(float2*)(C + (size_t)row1 * N + col) = make_float2(v2, v3);
        }
    }
}

// ---------------------------------------------------------------------------
// Masked attention (flash-style, fp32, parallel online softmax).
// 32 queries per block, 256 threads. float4 score/PV loops.
// Q/K/V in fused qkv buffer: row stride 3*DD, col offsets 0/DD/2*DD.
// Output tf32-rounded (feeds Wo GEMM).
// ---------------------------------------------------------------------------
#define QT 32
__global__ void __launch_bounds__(256) attn_kernel(
        const float* __restrict__ QKV, float* __restrict__ O) {
    __shared__ float4 Qs4[QT][17];      // 64 floats + 4 pad
    __shared__ float4 Ks4[64][16];
    __shared__ float4 Vs4[64][16];
    __shared__ float  Ss[QT][65];
    __shared__ float  red[QT][9];
    __shared__ float  mS[QT], lS[QT], scS[QT];

    const int qbase = blockIdx.x * QT;
    const int h  = blockIdx.y;
    const int b  = blockIdx.z;
    const int tid = threadIdx.x;
    const int RS = 3 * DD;

    // Load Q tile (32x64), pre-scaled by 1/sqrt(DK)=0.125
    for (int e = tid; e < QT * 16; e += 256) {
        int qi = e >> 4, d4 = e & 15;
        float4 qv = *((const float4*)(QKV + (size_t)(b * SS + qbase + qi) * RS + h * DKK) + d4);
        qv.x *= 0.125f; qv.y *= 0.125f; qv.z *= 0.125f; qv.w *= 0.125f;
        Qs4[qi][d4] = qv;
    }
    if (tid < QT) { mS[tid] = -INFINITY; lS[tid] = 0.0f; }

    const int sq = tid & 31;     // query (score & PV phases)
    const int sg = tid >> 5;     // key-group (8 keys) / dim-group (8 dims)
    float acc[8] = {0.f, 0.f, 0.f, 0.f, 0.f, 0.f, 0.f, 0.f};

    __syncthreads();

    for (int c = 0; c < SS / 64; c++) {
        bool use = (c == 0) || (qbase < NGLOBAL) ||
                   (64 * c + 63 >= qbase - WINDOW && 64 * c <= qbase + QT - 1 + WINDOW);
        if (!use) continue;

        __syncthreads();
        for (int e = tid; e < 64 * 16; e += 256) {
            int r = e >> 4, d4 = e & 15;
            const float4* src = (const float4*)(QKV + (size_t)(b * SS + 64 * c + r) * RS + h * DKK) + d4;
            Ks4[r][d4] = src[256];   // +DD floats
            Vs4[r][d4] = src[512];   // +2*DD floats
        }
        __syncthreads();

        // ---- scores: thread (sq, sg) -> keys sg*8..sg*8+7 for query sq ----
        float s[8] = {0.f, 0.f, 0.f, 0.f, 0.f, 0.f, 0.f, 0.f};
        #pragma unroll
        for (int d4 = 0; d4 < 16; d4++) {
            float4 q = Qs4[sq][d4];
            #pragma unroll
            for (int kk = 0; kk < 8; kk++) {
                float4 kv = Ks4[sg * 8 + kk][d4];
                s[kk] += q.x * kv.x + q.y * kv.y + q.z * kv.z + q.w * kv.w;
            }
        }
        const int i = qbase + sq;
        float pmax = -INFINITY;
        #pragma unroll
        for (int kk = 0; kk < 8; kk++) {
            const int j = 64 * c + sg * 8 + kk;
            const bool ok = (abs(i - j) <= WINDOW) || (i < NGLOBAL) || (j < NGLOBAL);
            if (!ok) s[kk] = -INFINITY;
            pmax = fmaxf(pmax, s[kk]);
        }
        red[sq][sg] = pmax;
        __syncthreads();

        if (tid < QT) {
            float mx = mS[tid];
            #pragma unroll
            for (int g2 = 0; g2 < 8; g2++) mx = fmaxf(mx, red[tid][g2]);
            scS[tid] = expf(mS[tid] - mx);
            mS[tid]  = mx;
        }
        __syncthreads();

        const float mx = mS[sq];
        float ps = 0.0f;
        #pragma unroll
        for (int kk = 0; kk < 8; kk++) {
            float p = expf(s[kk] - mx);
            Ss[sq][sg * 8 + kk] = p;
            ps += p;
        }
        red[sq][sg] = ps;
        __syncthreads();

        if (tid < QT) {
            float l = lS[tid] * scS[tid];
            #pragma unroll
            for (int g2 = 0; g2 < 8; g2++) l += red[tid][g2];
            lS[tid] = l;
        }
        __syncthreads();

        // ---- PV: thread (sq, sg) -> dims sg*8..sg*8+7 for query sq ----
        const float sc = scS[sq];
        #pragma unroll
        for (int dd = 0; dd < 8; dd++) acc[dd] *= sc;
        #pragma unroll 4
        for (int k2 = 0; k2 < 64; k2++) {
            const float p = Ss[sq][k2];
            float4 v0 = Vs4[k2][sg * 2];
            float4 v1 = Vs4[k2][sg * 2 + 1];
            acc[0] += p * v0.x; acc[1] += p * v0.y;
            acc[2] += p * v0.z; acc[3] += p * v0.w;
            acc[4] += p * v1.x; acc[5] += p * v1.y;
            acc[6] += p * v1.z; acc[7] += p * v1.w;
        }
    }

    const float inv = 1.0f / lS[sq];
    float* op = O + (size_t)(b * SS + qbase + sq) * DD + h * DKK + sg * 8;
    float4 o0 = make_float4(round_tf32(acc[0] * inv), round_tf32(acc[1] * inv),
                            round_tf32(acc[2] * inv), round_tf32(acc[3] * inv));
    float4 o1 = make_float4(round_tf32(acc[4] * inv), round_tf32(acc[5] * inv),
                            round_tf32(acc[6] * inv), round_tf32(acc[7] * inv));
    *(float4*)op = o0;
    *(float4*)(op + 4) = o1;
}

// ---------------------------------------------------------------------------
// Launch
// ---------------------------------------------------------------------------
extern "C" void kernel_launch(void* const* d_in, const int* in_sizes, int n_in,
                              void* d_out, int out_size) {
    const float* x     = (const float*)d_in[0];
    const float* Wq    = (const float*)d_in[1];
    const float* bq    = (const float*)d_in[2];
    const float* Wk    = (const float*)d_in[3];
    const float* bk    = (const float*)d_in[4];
    const float* Wv    = (const float*)d_in[5];
    const float* bv    = (const float*)d_in[6];
    const float* Wo    = (const float*)d_in[7];
    const float* bo    = (const float*)d_in[8];
    const float* ln1_g = (const float*)d_in[9];
    const float* ln1_b = (const float*)d_in[10];
    const float* W1    = (const float*)d_in[11];
    const float* b1    = (const float*)d_in[12];
    const float* W2    = (const float*)d_in[13];
    const float* b2    = (const float*)d_in[14];
    const float* ln2_g = (const float*)d_in[15];
    const float* ln2_b = (const float*)d_in[16];
    float* out = (float*)d_out;

    float *xn, *qkv, *att, *x1, *xn2, *hbuf, *wqkv, *wo, *w1, *w2, *bqkv;
    cudaGetSymbolAddress((void**)&xn,   g_xn);
    cudaGetSymbolAddress((void**)&qkv,  g_qkv);
    cudaGetSymbolAddress((void**)&att,  g_att);
    cudaGetSymbolAddress((void**)&x1,   g_x1);
    cudaGetSymbolAddress((void**)&xn2,  g_xn2);
    cudaGetSymbolAddress((void**)&hbuf, g_h);
    cudaGetSymbolAddress((void**)&wqkv, g_wqkv);
    cudaGetSymbolAddress((void**)&wo,   g_wo);
    cudaGetSymbolAddress((void**)&w1,   g_w1);
    cudaGetSymbolAddress((void**)&w2,   g_w2);
    cudaGetSymbolAddress((void**)&bqkv, g_bqkv);

    cudaFuncSetAttribute(gemm_tf32_kernel<0>,
        cudaFuncAttributeMaxDynamicSharedMemorySize, GEMM_SMEM_BYTES);
    cudaFuncSetAttribute(gemm_tf32_kernel<1>,
        cudaFuncAttributeMaxDynamicSharedMemorySize, GEMM_SMEM_BYTES);
    cudaFuncSetAttribute(gemm_tf32_kernel<2>,
        cudaFuncAttributeMaxDynamicSharedMemorySize, GEMM_SMEM_BYTES);

    // 0) fused prepass: round + concat weights (one launch)
    prep_kernel<<<(PREP_TOTAL + 255) / 256, 256>>>(
        (const float4*)Wq, (const float4*)Wk, (const float4*)Wv,
        (const float4*)Wo, (const float4*)W1, (const float4*)W2,
        (const float4*)bq, (const float4*)bk, (const float4*)bv,
        (float4*)wqkv, (float4*)wo, (float4*)w1, (float4*)w2, (float4*)bqkv);

    // 1) xn = LN(x)   (tf32-rounded)
    ln_kernel<<<MM, 256>>>(x, ln1_g, ln1_b, xn);

    // 2) qkv = xn @ Wqkv + bqkv   (one fused GEMM, N=3072)
    dim3 gq(3 * DD / 128, MM / 128);
    gemm_tf32_kernel<0><<<gq, 256, GEMM_SMEM_BYTES>>>(xn, wqkv, bqkv, nullptr,
                                                      qkv, MM, 3 * DD, DD);

    // 3) masked attention (tf32-rounded output)
    attn_kernel<<<dim3(SS / QT, HH, BB), 256>>>(qkv, att);

    // 4) x1 = x + att @ Wo + bo
    dim3 g1(DD / 128, MM / 128);
    gemm_tf32_kernel<2><<<g1, 256, GEMM_SMEM_BYTES>>>(att, wo, bo, x, x1, MM, DD, DD);

    // 5) xn2 = LN(x1)  (tf32-rounded)
    ln_kernel<<<MM, 256>>>(x1, ln2_g, ln2_b, xn2);

    // 6) h = gelu(xn2 @ W1 + b1)  (tf32-rounded)
    dim3 g2(DFF / 128, MM / 128);
    gemm_tf32_kernel<1><<<g2, 256, GEMM_SMEM_BYTES>>>(xn2, w1, b1, nullptr, hbuf, MM, DFF, DD);

    // 7) out = x1 + h @ W2 + b2
    gemm_tf32_kernel<2><<<g1, 256, GEMM_SMEM_BYTES>>>(hbuf, w2, b2, x1, out, MM, DD, DFF);
}

// round 6
// speedup vs baseline: 3.1413x; 1.1631x over previous
#include <cuda_runtime.h>
#include <math.h>
#include <stdint.h>

// ---------------------------------------------------------------------------
// Problem constants
// ---------------------------------------------------------------------------
#define BB 2
#define SS 2048
#define DD 1024
#define HH 16
#define DKK 64
#define DFF 4096
#define WINDOW 128
#define NGLOBAL 16
#define MM (BB * SS)   // 4096 rows

// ---------------------------------------------------------------------------
// Scratch (device globals; no allocation allowed)
// ---------------------------------------------------------------------------
__device__ float g_xn  [MM * DD];
__device__ float g_qkv [MM * 3 * DD];
__device__ float g_att [MM * DD];
__device__ float g_x1  [MM * DD];
__device__ float g_xn2 [MM * DD];
__device__ float g_h   [MM * DFF];
__device__ float g_wqkv[DD * 3 * DD];
__device__ float g_wo  [DD * DD];
__device__ float g_w1  [DD * DFF];
__device__ float g_w2  [DFF * DD];
__device__ float g_bqkv[3 * DD];

// ---------------------------------------------------------------------------
// PTX helpers
// ---------------------------------------------------------------------------
__device__ __forceinline__ float round_tf32(float x) {
    uint32_t r;
    asm("cvt.rna.tf32.f32 %0, %1;" : "=r"(r) : "f"(x));
    return __uint_as_float(r);
}
__device__ __forceinline__ float4 rtf4(float4 v) {
    v.x = round_tf32(v.x); v.y = round_tf32(v.y);
    v.z = round_tf32(v.z); v.w = round_tf32(v.w);
    return v;
}

__device__ __forceinline__ void mma_tf32(float c[4], const uint32_t a[4], const uint32_t b[2]) {
    asm volatile(
        "mma.sync.aligned.m16n8k8.row.col.f32.tf32.tf32.f32 "
        "{%0,%1,%2,%3}, {%4,%5,%6,%7}, {%8,%9}, {%0,%1,%2,%3};\n"
        : "+f"(c[0]), "+f"(c[1]), "+f"(c[2]), "+f"(c[3])
        : "r"(a[0]), "r"(a[1]), "r"(a[2]), "r"(a[3]), "r"(b[0]), "r"(b[1]));
}

__device__ __forceinline__ void cp_async16(float* smem_dst, const float* gmem_src) {
    uint32_t s = (uint32_t)__cvta_generic_to_shared(smem_dst);
    asm volatile("cp.async.cg.shared.global [%0], [%1], 16;\n" :: "r"(s), "l"(gmem_src));
}
__device__ __forceinline__ void cp_async_commit() {
    asm volatile("cp.async.commit_group;\n");
}
template<int N>
__device__ __forceinline__ void cp_async_wait() {
    asm volatile("cp.async.wait_group %0;\n" :: "n"(N));
}

__device__ __forceinline__ float gelu_exact(float x) {
    return 0.5f * x * (1.0f + erff(x * 0.70710678118654752f));
}

// ---------------------------------------------------------------------------
// Fused prepass: round weights to tf32 into staging buffers (float4), concat
// QKV weights + biases. One launch.
// ---------------------------------------------------------------------------
#define PREP_TOTAL 3146496
__global__ void __launch_bounds__(256) prep_kernel(
        const float4* __restrict__ Wq, const float4* __restrict__ Wk,
        const float4* __restrict__ Wv, const float4* __restrict__ Wo,
        const float4* __restrict__ W1, const float4* __restrict__ W2,
        const float4* __restrict__ bq, const float4* __restrict__ bk,
        const float4* __restrict__ bv,
        float4* __restrict__ wqkv, float4* __restrict__ wo,
        float4* __restrict__ w1, float4* __restrict__ w2,
        float4* __restrict__ bqkv) {
    int idx = blockIdx.x * 256 + threadIdx.x;
    if (idx < 786432) {
        int sub = idx >> 18;            // 0..2
        int k   = idx & 262143;
        int r   = k >> 8, c = k & 255;
        const float4* src = (sub == 0) ? Wq : (sub == 1) ? Wk : Wv;
        wqkv[r * 768 + sub * 256 + c] = rtf4(src[k]);
    } else if (idx < 1048576) {
        int k = idx - 786432;
        wo[k] = rtf4(Wo[k]);
    } else if (idx < 2097152) {
        int k = idx - 1048576;
        w1[k] = rtf4(W1[k]);
    } else if (idx < 3145728) {
        int k = idx - 2097152;
        w2[k] = rtf4(W2[k]);
    } else if (idx < PREP_TOTAL) {
        int k = idx - 3145728;          // 0..767
        int sub = k >> 8, c = k & 255;
        const float4* src = (sub == 0) ? bq : (sub == 1) ? bk : bv;
        bqkv[sub * 256 + c] = src[c];
    }
}

// ---------------------------------------------------------------------------
// LayerNorm: one block per row of 1024, 256 threads. Output tf32-rounded.
// ---------------------------------------------------------------------------
__device__ __forceinline__ float block_reduce_sum(float v, float* sh) {
    int lane = threadIdx.x & 31;
    int wid  = threadIdx.x >> 5;
    #pragma unroll
    for (int o = 16; o > 0; o >>= 1) v += __shfl_down_sync(0xffffffffu, v, o);
    if (lane == 0) sh[wid] = v;
    __syncthreads();
    if (wid == 0) {
        float t = (lane < 8) ? sh[lane] : 0.0f;
        #pragma unroll
        for (int o = 4; o > 0; o >>= 1) t += __shfl_down_sync(0xffffffffu, t, o);
        if (lane == 0) sh[0] = t;
    }
    __syncthreads();
    float r = sh[0];
    __syncthreads();
    return r;
}

__global__ void __launch_bounds__(256) ln_kernel(const float* __restrict__ x,
                                                 const float* __restrict__ g,
                                                 const float* __restrict__ b,
                                                 float* __restrict__ y) {
    __shared__ float sh[32];
    const int row = blockIdx.x;
    const float* xr = x + (size_t)row * DD;
    float v[4];
    float s = 0.0f;
    #pragma unroll
    for (int i = 0; i < 4; i++) { v[i] = xr[threadIdx.x + 256 * i]; s += v[i]; }
    s = block_reduce_sum(s, sh);
    const float mean = s * (1.0f / DD);
    float sq = 0.0f;
    #pragma unroll
    for (int i = 0; i < 4; i++) { float d = v[i] - mean; sq += d * d; }
    sq = block_reduce_sum(sq, sh);
    const float rstd = rsqrtf(sq * (1.0f / DD) + 1e-5f);
    float* yr = y + (size_t)row * DD;
    #pragma unroll
    for (int i = 0; i < 4; i++) {
        int c = threadIdx.x + 256 * i;
        yr[c] = round_tf32((v[i] - mean) * rstd * g[c] + b[c]);
    }
}

// ---------------------------------------------------------------------------
// TF32 tensor-core GEMM (unchanged from R5): C = A @ B + bias (+ epilogue)
// ---------------------------------------------------------------------------
#define AS_STRIDE 36
#define BS_STRIDE 136
#define AS_FLOATS (128 * AS_STRIDE)
#define BS_FLOATS (32 * BS_STRIDE)
#define STG_FLOATS (AS_FLOATS + BS_FLOATS)
#define GEMM_SMEM_BYTES (3 * STG_FLOATS * 4)

template<int EPI>
__global__ void __launch_bounds__(256, 2) gemm_tf32_kernel(
        const float* __restrict__ A, const float* __restrict__ B,
        const float* __restrict__ bias, const float* __restrict__ resid,
        float* __restrict__ C, int M, int N, int K) {
    extern __shared__ float smem[];

    const int bm = blockIdx.y * 128;
    const int bn = blockIdx.x * 128;
    const int tid  = threadIdx.x;
    const int warp = tid >> 5;
    const int lane = tid & 31;
    const int g    = lane >> 2;
    const int tig  = lane & 3;
    const int warp_m = (warp & 1) * 64;
    const int warp_n = (warp >> 1) * 32;

    float acc[4][4][4];
    #pragma unroll
    for (int mf = 0; mf < 4; mf++)
        #pragma unroll
        for (int nf = 0; nf < 4; nf++)
            #pragma unroll
            for (int r = 0; r < 4; r++) acc[mf][nf][r] = 0.0f;

    const int NK = K >> 5;

    auto load_tile = [&](int kt) {
        float* As = smem + (kt % 3) * STG_FLOATS;
        float* Bs = As + AS_FLOATS;
        const int k0 = kt << 5;
        #pragma unroll
        for (int i = 0; i < 4; i++) {
            int f = tid + 256 * i;
            int row = f >> 3, c4 = (f & 7) << 2;
            cp_async16(&As[row * AS_STRIDE + c4],
                       A + (size_t)(bm + row) * K + k0 + c4);
        }
        #pragma unroll
        for (int i = 0; i < 4; i++) {
            int f = tid + 256 * i;
            int row = f >> 5, c4 = (f & 31) << 2;
            cp_async16(&Bs[row * BS_STRIDE + c4],
                       B + (size_t)(k0 + row) * N + bn + c4);
        }
        cp_async_commit();
    };

    load_tile(0);
    load_tile(1);

    for (int kt = 0; kt < NK; kt++) {
        if (kt + 1 < NK) cp_async_wait<1>();
        else             cp_async_wait<0>();
        __syncthreads();
        if (kt + 2 < NK) load_tile(kt + 2);

        const float* As = smem + (kt % 3) * STG_FLOATS;
        const float* Bs = As + AS_FLOATS;

        #pragma unroll
        for (int ks = 0; ks < 4; ks++) {
            const int kk = ks << 3;
            uint32_t afrag[4][4], bfrag[4][2];
            #pragma unroll
            for (int mf = 0; mf < 4; mf++) {
                const int r0 = warp_m + mf * 16 + g;
                afrag[mf][0] = __float_as_uint(As[(r0    ) * AS_STRIDE + kk + tig    ]);
                afrag[mf][1] = __float_as_uint(As[(r0 + 8) * AS_STRIDE + kk + tig    ]);
                afrag[mf][2] = __float_as_uint(As[(r0    ) * AS_STRIDE + kk + tig + 4]);
                afrag[mf][3] = __float_as_uint(As[(r0 + 8) * AS_STRIDE + kk + tig + 4]);
            }
            #pragma unroll
            for (int nf = 0; nf < 4; nf++) {
                const int c0 = warp_n + nf * 8 + g;
                bfrag[nf][0] = __float_as_uint(Bs[(kk + tig    ) * BS_STRIDE + c0]);
                bfrag[nf][1] = __float_as_uint(Bs[(kk + tig + 4) * BS_STRIDE + c0]);
            }
            #pragma unroll
            for (int mf = 0; mf < 4; mf++)
                #pragma unroll
                for (int nf = 0; nf < 4; nf++)
                    mma_tf32(acc[mf][nf], afrag[mf], bfrag[nf]);
        }
    }

    #pragma unroll
    for (int mf = 0; mf < 4; mf++) {
        #pragma unroll
        for (int nf = 0; nf < 4; nf++) {
            const int row0 = bm + warp_m + mf * 16 + g;
            const int row1 = row0 + 8;
            const int col  = bn + warp_n + nf * 8 + 2 * tig;
            const float b0 = bias[col], b1 = bias[col + 1];
            float v0 = acc[mf][nf][0] + b0;
            float v1 = acc[mf][nf][1] + b1;
            float v2 = acc[mf][nf][2] + b0;
            float v3 = acc[mf][nf][3] + b1;
            if (EPI == 1) {
                v0 = round_tf32(gelu_exact(v0)); v1 = round_tf32(gelu_exact(v1));
                v2 = round_tf32(gelu_exact(v2)); v3 = round_tf32(gelu_exact(v3));
            }
            if (EPI == 2) {
                float2 r0v = *(const float2*)(resid + (size_t)row0 * N + col);
                float2 r1v = *(const float2*)(resid + (size_t)row1 * N + col);
                v0 += r0v.x; v1 += r0v.y; v2 += r1v.x; v3 += r1v.y;
            }
            *(float2*)(C + (size_t)row0 * N + col) = make_float2(v0, v1);
            *(float2*)(C + (size_t)row1 * N + col) = make_float2(v2, v3);
        }
    }
}

// ---------------------------------------------------------------------------
// Tensor-core masked flash attention (tf32 mma for QK^T and P@V).
// 64 queries/block, 256 threads (8 warps, 4x2 quadrants of the 64x64 S tile).
// Online softmax, fully parallel. V stored transposed in smem for the
// row.col PV mma. Output tf32-rounded.
// ---------------------------------------------------------------------------
#define QT 64
#define CH 64
// dynamic smem layout (floats)
#define O_QS  0                       // [64][68]
#define O_KS  4352                    // [64][68]
#define O_VT  8704                    // [64][65]
#define O_PS  12864                   // [64][68]
#define O_RED 17216                   // [64][4]
#define O_M   17472
#define O_L   17536
#define O_SC  17600
#define ATTN_SMEM_FLOATS 17664
#define ATTN_SMEM_BYTES (ATTN_SMEM_FLOATS * 4)   // 70656

__global__ void __launch_bounds__(256) attn_kernel(
        const float* __restrict__ QKV, float* __restrict__ O) {
    extern __shared__ float dyn[];
    float* Qs = dyn + O_QS;
    float* Ks = dyn + O_KS;
    float* Vt = dyn + O_VT;
    float* Ps = dyn + O_PS;
    float* red = dyn + O_RED;
    float* mS = dyn + O_M;
    float* lS = dyn + O_L;
    float* scS = dyn + O_SC;

    const int qbase = blockIdx.x * QT;
    const int h  = blockIdx.y;
    const int b  = blockIdx.z;
    const int tid = threadIdx.x;
    const int warp = tid >> 5, lane = tid & 31;
    const int g = lane >> 2, tig = lane & 3;
    const int m0 = (warp >> 1) * 16;     // S row quadrant (0,16,32,48)
    const int n0 = (warp & 1) * 32;      // S col quadrant (0,32)
    const int RS = 3 * DD;

    // ---- load Q (64x64), scaled + tf32-rounded ----
    #pragma unroll
    for (int it = 0; it < 4; it++) {
        int e = tid + it * 256;          // < 1024
        int qi = e >> 4, d4 = e & 15;
        float4 qv = *((const float4*)(QKV + (size_t)(b * SS + qbase + qi) * RS + h * DKK) + d4);
        qv.x = round_tf32(qv.x * 0.125f); qv.y = round_tf32(qv.y * 0.125f);
        qv.z = round_tf32(qv.z * 0.125f); qv.w = round_tf32(qv.w * 0.125f);
        *(float4*)&Qs[qi * 68 + d4 * 4] = qv;
    }
    if (tid < QT) { mS[tid] = -INFINITY; lS[tid] = 0.0f; }

    float o_acc[4][4];
    #pragma unroll
    for (int nf = 0; nf < 4; nf++)
        #pragma unroll
        for (int r = 0; r < 4; r++) o_acc[nf][r] = 0.0f;

    const int sq = tid & 63;     // softmax row
    const int cg = tid >> 6;     // softmax col group (16 cols)

    __syncthreads();

    for (int c = 0; c < SS / CH; c++) {
        bool use = (c == 0) || (qbase < NGLOBAL) ||
                   (CH * c + CH - 1 >= qbase - WINDOW && CH * c <= qbase + QT - 1 + WINDOW);
        if (!use) continue;

        __syncthreads();   // prior chunk fully consumed

        // ---- load K (rows=key) and V transposed (rows=dim), tf32-rounded ----
        #pragma unroll
        for (int it = 0; it < 4; it++) {
            int e = tid + it * 256;      // < 1024
            int r = e >> 4, d4 = e & 15;
            const float4* src = (const float4*)(QKV + (size_t)(b * SS + CH * c + r) * RS + h * DKK) + d4;
            float4 kv = rtf4(src[256]);          // +DD
            *(float4*)&Ks[r * 68 + d4 * 4] = kv;
            float4 vv = rtf4(src[512]);          // +2*DD
            Vt[(d4 * 4 + 0) * 65 + r] = vv.x;
            Vt[(d4 * 4 + 1) * 65 + r] = vv.y;
            Vt[(d4 * 4 + 2) * 65 + r] = vv.z;
            Vt[(d4 * 4 + 3) * 65 + r] = vv.w;
        }
        __syncthreads();

        // ---- S = Q @ K^T (warp quadrant m16 x n32) ----
        float s_acc[4][4];
        #pragma unroll
        for (int nf = 0; nf < 4; nf++)
            #pragma unroll
            for (int r = 0; r < 4; r++) s_acc[nf][r] = 0.0f;
        #pragma unroll
        for (int ks = 0; ks < 8; ks++) {
            const int kk = ks << 3;
            uint32_t a[4];
            a[0] = __float_as_uint(Qs[(m0 + g    ) * 68 + kk + tig    ]);
            a[1] = __float_as_uint(Qs[(m0 + g + 8) * 68 + kk + tig    ]);
            a[2] = __float_as_uint(Qs[(m0 + g    ) * 68 + kk + tig + 4]);
            a[3] = __float_as_uint(Qs[(m0 + g + 8) * 68 + kk + tig + 4]);
            #pragma unroll
            for (int nf = 0; nf < 4; nf++) {
                uint32_t bb[2];
                bb[0] = __float_as_uint(Ks[(n0 + nf * 8 + g) * 68 + kk + tig    ]);
                bb[1] = __float_as_uint(Ks[(n0 + nf * 8 + g) * 68 + kk + tig + 4]);
                mma_tf32(s_acc[nf], a, bb);
            }
        }
        // store S
        #pragma unroll
        for (int nf = 0; nf < 4; nf++) {
            const int col = n0 + nf * 8 + 2 * tig;
            *(float2*)&Ps[(m0 + g    ) * 68 + col] = make_float2(s_acc[nf][0], s_acc[nf][1]);
            *(float2*)&Ps[(m0 + g + 8) * 68 + col] = make_float2(s_acc[nf][2], s_acc[nf][3]);
        }
        __syncthreads();

        // ---- softmax phase A: mask + row max (thread: row sq, 16 cols) ----
        const int i = qbase + sq;
        float4 sv[4];
        float pmax = -INFINITY;
        #pragma unroll
        for (int j4 = 0; j4 < 4; j4++) {
            float4 s = *(const float4*)&Ps[sq * 68 + cg * 16 + j4 * 4];
            const int j = CH * c + cg * 16 + j4 * 4;
            const bool gi = (i < NGLOBAL);
            if (!(gi || abs(i - (j + 0)) <= WINDOW || (j + 0) < NGLOBAL)) s.x = -INFINITY;
            if (!(gi || abs(i - (j + 1)) <= WINDOW || (j + 1) < NGLOBAL)) s.y = -INFINITY;
            if (!(gi || abs(i - (j + 2)) <= WINDOW || (j + 2) < NGLOBAL)) s.z = -INFINITY;
            if (!(gi || abs(i - (j + 3)) <= WINDOW || (j + 3) < NGLOBAL)) s.w = -INFINITY;
            sv[j4] = s;
            pmax = fmaxf(pmax, fmaxf(fmaxf(s.x, s.y), fmaxf(s.z, s.w)));
        }
        red[sq * 4 + cg] = pmax;
        __syncthreads();

        if (tid < QT) {
            float mx = fmaxf(fmaxf(red[tid * 4], red[tid * 4 + 1]),
                             fmaxf(red[tid * 4 + 2], red[tid * 4 + 3]));
            mx = fmaxf(mx, mS[tid]);
            scS[tid] = __expf(mS[tid] - mx);
            mS[tid]  = mx;
        }
        __syncthreads();

        // ---- exp + partial sums; store tf32-rounded probs ----
        const float mx = mS[sq];
        float ps = 0.0f;
        #pragma unroll
        for (int j4 = 0; j4 < 4; j4++) {
            float4 p;
            p.x = round_tf32(__expf(sv[j4].x - mx));
            p.y = round_tf32(__expf(sv[j4].y - mx));
            p.z = round_tf32(__expf(sv[j4].z - mx));
            p.w = round_tf32(__expf(sv[j4].w - mx));
            ps += p.x + p.y + p.z + p.w;
            *(float4*)&Ps[sq * 68 + cg * 16 + j4 * 4] = p;
        }
        red[sq * 4 + cg] = ps;
        __syncthreads();

        if (tid < QT)
            lS[tid] = lS[tid] * scS[tid] + red[tid * 4] + red[tid * 4 + 1]
                      + red[tid * 4 + 2] + red[tid * 4 + 3];

        // ---- O = O*sc + P @ V (warp quadrant rows m0, dims n0) ----
        const float sc0 = scS[m0 + g], sc1 = scS[m0 + g + 8];
        #pragma unroll
        for (int nf = 0; nf < 4; nf++) {
            o_acc[nf][0] *= sc0; o_acc[nf][1] *= sc0;
            o_acc[nf][2] *= sc1; o_acc[nf][3] *= sc1;
        }
        #pragma unroll
        for (int ks = 0; ks < 8; ks++) {
            const int kk = ks << 3;
            uint32_t a[4];
            a[0] = __float_as_uint(Ps[(m0 + g    ) * 68 + kk + tig    ]);
            a[1] = __float_as_uint(Ps[(m0 + g + 8) * 68 + kk + tig    ]);
            a[2] = __float_as_uint(Ps[(m0 + g    ) * 68 + kk + tig + 4]);
            a[3] = __float_as_uint(Ps[(m0 + g + 8) * 68 + kk + tig + 4]);
            #pragma unroll
            for (int nf = 0; nf < 4; nf++) {
                uint32_t bb[2];
                bb[0] = __float_as_uint(Vt[(n0 + nf * 8 + g) * 65 + kk + tig    ]);
                bb[1] = __float_as_uint(Vt[(n0 + nf * 8 + g) * 65 + kk + tig + 4]);
                mma_tf32(o_acc[nf], a, bb);
            }
        }
    }

    __syncthreads();
    const float inv0 = 1.0f / lS[m0 + g];
    const float inv1 = 1.0f / lS[m0 + g + 8];
    #pragma unroll
    for (int nf = 0; nf < 4; nf++) {
        const int col = h * DKK + n0 + nf * 8 + 2 * tig;
        float* o0 = O + (size_t)(b * SS + qbase + m0 + g    ) * DD + col;
        float* o1 = O + (size_t)(b * SS + qbase + m0 + g + 8) * DD + col;
        *(float2*)o0 = make_float2(round_tf32(o_acc[nf][0] * inv0),
                                   round_tf32(o_acc[nf][1] * inv0));
        *(float2*)o1 = make_float2(round_tf32(o_acc[nf][2] * inv1),
                                   round_tf32(o_acc[nf][3] * inv1));
    }
}

// ---------------------------------------------------------------------------
// Launch
// ---------------------------------------------------------------------------
extern "C" void kernel_launch(void* const* d_in, const int* in_sizes, int n_in,
                              void* d_out, int out_size) {
    const float* x     = (const float*)d_in[0];
    const float* Wq    = (const float*)d_in[1];
    const float* bq    = (const float*)d_in[2];
    const float* Wk    = (const float*)d_in[3];
    const float* bk    = (const float*)d_in[4];
    const float* Wv    = (const float*)d_in[5];
    const float* bv    = (const float*)d_in[6];
    const float* Wo    = (const float*)d_in[7];
    const float* bo    = (const float*)d_in[8];
    const float* ln1_g = (const float*)d_in[9];
    const float* ln1_b = (const float*)d_in[10];
    const float* W1    = (const float*)d_in[11];
    const float* b1    = (const float*)d_in[12];
    const float* W2    = (const float*)d_in[13];
    const float* b2    = (const float*)d_in[14];
    const float* ln2_g = (const float*)d_in[15];
    const float* ln2_b = (const float*)d_in[16];
    float* out = (float*)d_out;

    float *xn, *qkv, *att, *x1, *xn2, *hbuf, *wqkv, *wo, *w1, *w2, *bqkv;
    cudaGetSymbolAddress((void**)&xn,   g_xn);
    cudaGetSymbolAddress((void**)&qkv,  g_qkv);
    cudaGetSymbolAddress((void**)&att,  g_att);
    cudaGetSymbolAddress((void**)&x1,   g_x1);
    cudaGetSymbolAddress((void**)&xn2,  g_xn2);
    cudaGetSymbolAddress((void**)&hbuf, g_h);
    cudaGetSymbolAddress((void**)&wqkv, g_wqkv);
    cudaGetSymbolAddress((void**)&wo,   g_wo);
    cudaGetSymbolAddress((void**)&w1,   g_w1);
    cudaGetSymbolAddress((void**)&w2,   g_w2);
    cudaGetSymbolAddress((void**)&bqkv, g_bqkv);

    cudaFuncSetAttribute(gemm_tf32_kernel<0>,
        cudaFuncAttributeMaxDynamicSharedMemorySize, GEMM_SMEM_BYTES);
    cudaFuncSetAttribute(gemm_tf32_kernel<1>,
        cudaFuncAttributeMaxDynamicSharedMemorySize, GEMM_SMEM_BYTES);
    cudaFuncSetAttribute(gemm_tf32_kernel<2>,
        cudaFuncAttributeMaxDynamicSharedMemorySize, GEMM_SMEM_BYTES);
    cudaFuncSetAttribute(attn_kernel,
        cudaFuncAttributeMaxDynamicSharedMemorySize, ATTN_SMEM_BYTES);

    // 0) fused prepass: round + concat weights
    prep_kernel<<<(PREP_TOTAL + 255) / 256, 256>>>(
        (const float4*)Wq, (const float4*)Wk, (const float4*)Wv,
        (const float4*)Wo, (const float4*)W1, (const float4*)W2,
        (const float4*)bq, (const float4*)bk, (const float4*)bv,
        (float4*)wqkv, (float4*)wo, (float4*)w1, (float4*)w2, (float4*)bqkv);

    // 1) xn = LN(x)
    ln_kernel<<<MM, 256>>>(x, ln1_g, ln1_b, xn);

    // 2) qkv = xn @ Wqkv + bqkv
    dim3 gq(3 * DD / 128, MM / 128);
    gemm_tf32_kernel<0><<<gq, 256, GEMM_SMEM_BYTES>>>(xn, wqkv, bqkv, nullptr,
                                                      qkv, MM, 3 * DD, DD);

    // 3) tensor-core masked attention
    attn_kernel<<<dim3(SS / QT, HH, BB), 256, ATTN_SMEM_BYTES>>>(qkv, att);

    // 4) x1 = x + att @ Wo + bo
    dim3 g1(DD / 128, MM / 128);
    gemm_tf32_kernel<2><<<g1, 256, GEMM_SMEM_BYTES>>>(att, wo, bo, x, x1, MM, DD, DD);

    // 5) xn2 = LN(x1)
    ln_kernel<<<MM, 256>>>(x1, ln2_g, ln2_b, xn2);

    // 6) h = gelu(xn2 @ W1 + b1)
    dim3 g2(DFF / 128, MM / 128);
    gemm_tf32_kernel<1><<<g2, 256, GEMM_SMEM_BYTES>>>(xn2, w1, b1, nullptr, hbuf, MM, DFF, DD);

    // 7) out = x1 + h @ W2 + b2
    gemm_tf32_kernel<2><<<g1, 256, GEMM_SMEM_BYTES>>>(hbuf, w2, b2, x1, out, MM, DD, DFF);
}